// round 1
// baseline (speedup 1.0000x reference)
#include <cuda_runtime.h>

#define BATCH   4
#define SEQ     4096
#define DIN     1024
#define DINNER  128
#define DOUT    1024
#define QKVN    384            // 3 * DINNER
#define M_TOTAL (BATCH * SEQ)  // 16384
#define SCALE   0.08838834764831845f  // 1/sqrt(128)

// Scratch (device globals are the sanctioned way to get scratch)
__device__ float g_qkv[(size_t)M_TOTAL * QKVN];   // [m, 384]: q|k|v
__device__ float g_ao [(size_t)M_TOTAL * DINNER]; // attention output [m, 128]

// ---------------------------------------------------------------------------
// Generic tiled GEMM:  C[m,n] = sum_k A[m,k] * B[n,k]  (+ bias[n])
// A: row-major [M,K], B: row-major [N,K] (i.e. we multiply by B^T), C: [M,N]
// BM=BN=BK=64, 256 threads, 4x4 register microtile per thread.
// ---------------------------------------------------------------------------
__global__ __launch_bounds__(256) void gemm_kt(
    const float* __restrict__ A, const float* __restrict__ B,
    const float* __restrict__ bias, float* __restrict__ C,
    int M, int N, int K)
{
    __shared__ float sA[64][68];
    __shared__ float sB[64][68];

    const int bm = blockIdx.y * 64;
    const int bn = blockIdx.x * 64;
    const int tid = threadIdx.x;
    const int ty = tid >> 4;   // 0..15
    const int tx = tid & 15;   // 0..15

    float acc[4][4] = {};

    for (int k0 = 0; k0 < K; k0 += 64) {
        // Load 64x64 A tile and 64x64 B tile (float4 per thread per pass)
        #pragma unroll
        for (int i = tid * 4; i < 64 * 64; i += 256 * 4) {
            int r = i >> 6, c = i & 63;
            float4 va = *(const float4*)(A + (size_t)(bm + r) * K + k0 + c);
            *(float4*)&sA[r][c] = va;
            float4 vb = *(const float4*)(B + (size_t)(bn + r) * K + k0 + c);
            *(float4*)&sB[r][c] = vb;
        }
        __syncthreads();

        #pragma unroll 8
        for (int kk = 0; kk < 64; kk += 4) {
            float4 a[4], b[4];
            #pragma unroll
            for (int r = 0; r < 4; r++) a[r] = *(float4*)&sA[ty * 4 + r][kk];
            #pragma unroll
            for (int c = 0; c < 4; c++) b[c] = *(float4*)&sB[tx * 4 + c][kk];
            #pragma unroll
            for (int r = 0; r < 4; r++)
                #pragma unroll
                for (int c = 0; c < 4; c++)
                    acc[r][c] += a[r].x * b[c].x + a[r].y * b[c].y
                               + a[r].z * b[c].z + a[r].w * b[c].w;
        }
        __syncthreads();
    }

    #pragma unroll
    for (int r = 0; r < 4; r++) {
        int row = bm + ty * 4 + r;
        int col = bn + tx * 4;
        float4 v;
        v.x = acc[r][0]; v.y = acc[r][1]; v.z = acc[r][2]; v.w = acc[r][3];
        if (bias) {
            v.x += bias[col + 0]; v.y += bias[col + 1];
            v.z += bias[col + 2]; v.w += bias[col + 3];
        }
        *(float4*)(C + (size_t)row * N + col) = v;
    }
}

// ---------------------------------------------------------------------------
// Flash attention (causal), fp32.
// Block: 256 threads, handles 64 query rows; iterates 64-key tiles.
// Dynamic smem: Q[64][132], K[64][132], V[64][132], S[64][64], m/l/scale[64].
// ---------------------------------------------------------------------------
#define QPAD 132
#define ATTN_SMEM_FLOATS (3 * 64 * QPAD + 64 * 64 + 3 * 64)
#define ATTN_SMEM_BYTES  (ATTN_SMEM_FLOATS * 4)

__global__ __launch_bounds__(256) void attn_kernel(
    const float* __restrict__ qkv, float* __restrict__ out)
{
    extern __shared__ float smem[];
    float* sQ = smem;                 // 64 x 132
    float* sK = sQ + 64 * QPAD;       // 64 x 132
    float* sV = sK + 64 * QPAD;       // 64 x 132
    float* sS = sV + 64 * QPAD;       // 64 x 64
    float* sM = sS + 64 * 64;         // 64
    float* sL = sM + 64;              // 64
    float* sScale = sL + 64;          // 64

    const int b   = blockIdx.y;
    const int qb  = blockIdx.x;
    const int tid = threadIdx.x;
    const int ty  = tid >> 4;         // 0..15
    const int tx  = tid & 15;         // 0..15
    const int q0  = qb * 64;

    const float* base = qkv + (size_t)b * SEQ * QKVN;

    // Load Q tile (pre-scaled by 1/sqrt(d))
    #pragma unroll
    for (int i = tid * 4; i < 64 * DINNER; i += 256 * 4) {
        int r = i >> 7, c = i & 127;
        float4 v = *(const float4*)(base + (size_t)(q0 + r) * QKVN + c);
        v.x *= SCALE; v.y *= SCALE; v.z *= SCALE; v.w *= SCALE;
        *(float4*)&sQ[r * QPAD + c] = v;
    }
    if (tid < 64) { sM[tid] = -1e30f; sL[tid] = 0.f; }

    float oacc[4][8] = {};
    __syncthreads();

    for (int kb = 0; kb <= qb; kb++) {
        const int k0 = kb * 64;
        // Load K and V tiles
        #pragma unroll
        for (int i = tid * 4; i < 64 * DINNER; i += 256 * 4) {
            int r = i >> 7, c = i & 127;
            const float* rowp = base + (size_t)(k0 + r) * QKVN;
            *(float4*)&sK[r * QPAD + c] = *(const float4*)(rowp + 128 + c);
            *(float4*)&sV[r * QPAD + c] = *(const float4*)(rowp + 256 + c);
        }
        __syncthreads();

        // S = Q K^T  (4x4 microtile per thread)
        float s[4][4] = {};
        #pragma unroll 8
        for (int kk = 0; kk < 128; kk += 4) {
            float4 a[4], bb[4];
            #pragma unroll
            for (int r = 0; r < 4; r++) a[r]  = *(float4*)&sQ[(ty * 4 + r) * QPAD + kk];
            #pragma unroll
            for (int c = 0; c < 4; c++) bb[c] = *(float4*)&sK[(tx * 4 + c) * QPAD + kk];
            #pragma unroll
            for (int r = 0; r < 4; r++)
                #pragma unroll
                for (int c = 0; c < 4; c++)
                    s[r][c] += a[r].x * bb[c].x + a[r].y * bb[c].y
                             + a[r].z * bb[c].z + a[r].w * bb[c].w;
        }

        // Write S to smem with causal mask on the diagonal tile
        const bool diag = (kb == qb);
        #pragma unroll
        for (int r = 0; r < 4; r++) {
            int gr = q0 + ty * 4 + r;
            #pragma unroll
            for (int c = 0; c < 4; c++) {
                int gc = k0 + tx * 4 + c;
                float v = s[r][c];
                if (diag && gc > gr) v = -1e30f;
                sS[(ty * 4 + r) * 64 + tx * 4 + c] = v;
            }
        }
        __syncthreads();

        // Online softmax: 4 threads per row
        {
            int row = tid >> 2, q4 = tid & 3;
            float mx = -1e30f;
            #pragma unroll
            for (int c = q4 * 16; c < q4 * 16 + 16; c++)
                mx = fmaxf(mx, sS[row * 64 + c]);
            mx = fmaxf(mx, __shfl_xor_sync(0xffffffffu, mx, 1));
            mx = fmaxf(mx, __shfl_xor_sync(0xffffffffu, mx, 2));
            float m_old = sM[row];
            float m_new = fmaxf(m_old, mx);
            float sum = 0.f;
            #pragma unroll
            for (int c = q4 * 16; c < q4 * 16 + 16; c++) {
                float p = __expf(sS[row * 64 + c] - m_new);
                sS[row * 64 + c] = p;
                sum += p;
            }
            sum += __shfl_xor_sync(0xffffffffu, sum, 1);
            sum += __shfl_xor_sync(0xffffffffu, sum, 2);
            if (q4 == 0) {
                float sc = __expf(m_old - m_new);
                sScale[row] = sc;
                sL[row] = sL[row] * sc + sum;
                sM[row] = m_new;
            }
        }
        __syncthreads();

        // Rescale O, then O += P @ V
        {
            #pragma unroll
            for (int r = 0; r < 4; r++) {
                float sc = sScale[ty * 4 + r];
                #pragma unroll
                for (int c = 0; c < 8; c++) oacc[r][c] *= sc;
            }
            #pragma unroll 2
            for (int j = 0; j < 64; j++) {
                float p0 = sS[(ty * 4 + 0) * 64 + j];
                float p1 = sS[(ty * 4 + 1) * 64 + j];
                float p2 = sS[(ty * 4 + 2) * 64 + j];
                float p3 = sS[(ty * 4 + 3) * 64 + j];
                float4 va = *(float4*)&sV[j * QPAD + tx * 8];
                float4 vb = *(float4*)&sV[j * QPAD + tx * 8 + 4];
                oacc[0][0] += p0 * va.x; oacc[0][1] += p0 * va.y;
                oacc[0][2] += p0 * va.z; oacc[0][3] += p0 * va.w;
                oacc[0][4] += p0 * vb.x; oacc[0][5] += p0 * vb.y;
                oacc[0][6] += p0 * vb.z; oacc[0][7] += p0 * vb.w;
                oacc[1][0] += p1 * va.x; oacc[1][1] += p1 * va.y;
                oacc[1][2] += p1 * va.z; oacc[1][3] += p1 * va.w;
                oacc[1][4] += p1 * vb.x; oacc[1][5] += p1 * vb.y;
                oacc[1][6] += p1 * vb.z; oacc[1][7] += p1 * vb.w;
                oacc[2][0] += p2 * va.x; oacc[2][1] += p2 * va.y;
                oacc[2][2] += p2 * va.z; oacc[2][3] += p2 * va.w;
                oacc[2][4] += p2 * vb.x; oacc[2][5] += p2 * vb.y;
                oacc[2][6] += p2 * vb.z; oacc[2][7] += p2 * vb.w;
                oacc[3][0] += p3 * va.x; oacc[3][1] += p3 * va.y;
                oacc[3][2] += p3 * va.z; oacc[3][3] += p3 * va.w;
                oacc[3][4] += p3 * vb.x; oacc[3][5] += p3 * vb.y;
                oacc[3][6] += p3 * vb.z; oacc[3][7] += p3 * vb.w;
            }
        }
        __syncthreads();
    }

    // Epilogue: normalize and store
    #pragma unroll
    for (int r = 0; r < 4; r++) {
        float inv = 1.f / sL[ty * 4 + r];
        float4 va, vb;
        va.x = oacc[r][0] * inv; va.y = oacc[r][1] * inv;
        va.z = oacc[r][2] * inv; va.w = oacc[r][3] * inv;
        vb.x = oacc[r][4] * inv; vb.y = oacc[r][5] * inv;
        vb.z = oacc[r][6] * inv; vb.w = oacc[r][7] * inv;
        size_t row = (size_t)b * SEQ + q0 + ty * 4 + r;
        *(float4*)(out + row * DINNER + tx * 8)     = va;
        *(float4*)(out + row * DINNER + tx * 8 + 4) = vb;
    }
}

// ---------------------------------------------------------------------------
extern "C" void kernel_launch(void* const* d_in, const int* in_sizes, int n_in,
                              void* d_out, int out_size)
{
    const float* x     = (const float*)d_in[0];
    const float* w_qkv = (const float*)d_in[1];
    const float* w_out = (const float*)d_in[2];
    const float* b_out = (const float*)d_in[3];
    float* out = (float*)d_out;

    float *qkv_p = nullptr, *ao_p = nullptr;
    cudaGetSymbolAddress((void**)&qkv_p, g_qkv);
    cudaGetSymbolAddress((void**)&ao_p, g_ao);

    cudaFuncSetAttribute(attn_kernel,
                         cudaFuncAttributeMaxDynamicSharedMemorySize,
                         ATTN_SMEM_BYTES);

    // 1) QKV projection: [16384,1024] x [384,1024]^T -> [16384,384]
    gemm_kt<<<dim3(QKVN / 64, M_TOTAL / 64), 256>>>(
        x, w_qkv, nullptr, qkv_p, M_TOTAL, QKVN, DIN);

    // 2) Causal flash attention -> [16384,128]
    attn_kernel<<<dim3(SEQ / 64, BATCH), 256, ATTN_SMEM_BYTES>>>(qkv_p, ao_p);

    // 3) Output projection + bias: [16384,128] x [1024,128]^T -> [16384,1024]
    gemm_kt<<<dim3(DOUT / 64, M_TOTAL / 64), 256>>>(
        ao_p, w_out, b_out, out, M_TOTAL, DOUT, DINNER);
}

// round 3
// speedup vs baseline: 1.4830x; 1.4830x over previous
#include <cuda_runtime.h>
#include <cuda_bf16.h>
#include <cstdint>

#define BATCH   4
#define SEQ     4096
#define DIN     1024
#define DINNER  128
#define DOUT    1024
#define QKVN    384
#define M_TOTAL (BATCH * SEQ)
#define SCALE   0.08838834764831845f

__device__ float g_qkv[(size_t)M_TOTAL * QKVN];
__device__ float g_ao [(size_t)M_TOTAL * DINNER];

// ---------------------------------------------------------------------------
// Helpers (generic PTX only: ldmatrix sm_75+, mma.sync sm_80+)
// ---------------------------------------------------------------------------
__device__ __forceinline__ uint32_t smem_u32(const void* p) {
    uint32_t a;
    asm("{ .reg .u64 t; cvta.to.shared.u64 t, %1; cvt.u32.u64 %0, t; }"
        : "=r"(a) : "l"(p));
    return a;
}
__device__ __forceinline__ void ldsm4(uint32_t* r, uint32_t a) {
    asm volatile("ldmatrix.sync.aligned.m8n8.x4.shared.b16 {%0,%1,%2,%3}, [%4];"
        : "=r"(r[0]), "=r"(r[1]), "=r"(r[2]), "=r"(r[3]) : "r"(a));
}
__device__ __forceinline__ void ldsm2(uint32_t* r, uint32_t a) {
    asm volatile("ldmatrix.sync.aligned.m8n8.x2.shared.b16 {%0,%1}, [%2];"
        : "=r"(r[0]), "=r"(r[1]) : "r"(a));
}
__device__ __forceinline__ void mma16816(float* c, const uint32_t* a,
                                         const uint32_t* b) {
    asm volatile(
        "mma.sync.aligned.m16n8k16.row.col.f32.bf16.bf16.f32 "
        "{%0,%1,%2,%3}, {%4,%5,%6,%7}, {%8,%9}, {%0,%1,%2,%3};"
        : "+f"(c[0]), "+f"(c[1]), "+f"(c[2]), "+f"(c[3])
        : "r"(a[0]), "r"(a[1]), "r"(a[2]), "r"(a[3]), "r"(b[0]), "r"(b[1]));
}
// Split fp32x4 into bf16 hi/lo and store 8B each.
__device__ __forceinline__ void cvt_store(float4 f, __nv_bfloat16* hp,
                                          __nv_bfloat16* lp) {
    __nv_bfloat162 h01 = __floats2bfloat162_rn(f.x, f.y);
    __nv_bfloat162 h23 = __floats2bfloat162_rn(f.z, f.w);
    float lx = f.x - __bfloat162float(h01.x);
    float ly = f.y - __bfloat162float(h01.y);
    float lz = f.z - __bfloat162float(h23.x);
    float lw = f.w - __bfloat162float(h23.y);
    __nv_bfloat162 l01 = __floats2bfloat162_rn(lx, ly);
    __nv_bfloat162 l23 = __floats2bfloat162_rn(lz, lw);
    uint2 hv, lv;
    hv.x = *(uint32_t*)&h01; hv.y = *(uint32_t*)&h23;
    lv.x = *(uint32_t*)&l01; lv.y = *(uint32_t*)&l23;
    *(uint2*)hp = hv;
    *(uint2*)lp = lv;
}

// ---------------------------------------------------------------------------
// Tensor-core GEMM via mma.sync, bf16x3 split precision.
//   C[m,n] = sum_k A[m,k]*B[n,k] (+bias[n]); A:[M,K] fp32, B:[N,K] fp32.
// Block tile 128x128x32, 8 warps (warp tile 64x32).
// ---------------------------------------------------------------------------
#define PITCH 40  // bf16 elements per smem row (80B: conflict-free ldmatrix)

__global__ __launch_bounds__(256) void gemm_mma(
    const float* __restrict__ A, const float* __restrict__ B,
    const float* __restrict__ bias, float* __restrict__ C,
    int K, int N)
{
    __shared__ __nv_bfloat16 sAh[128 * PITCH], sAl[128 * PITCH];
    __shared__ __nv_bfloat16 sBh[128 * PITCH], sBl[128 * PITCH];

    const int tid = threadIdx.x;
    const int lid = tid & 31, wid = tid >> 5;
    const int m0 = blockIdx.y * 128, n0 = blockIdx.x * 128;
    const int mbase = (wid & 1) * 64, nbase = (wid >> 1) * 32;

    const uint32_t aAh = smem_u32(sAh), aAl = smem_u32(sAl);
    const uint32_t aBh = smem_u32(sBh), aBl = smem_u32(sBl);
    const int l8 = lid & 7, lbit = (lid >> 3) & 1, lk = lid >> 4;

    float acc[4][4][4] = {};

    const int ldrow = tid >> 3, ldc4 = tid & 7;

    for (int k0 = 0; k0 < K; k0 += 32) {
        #pragma unroll
        for (int p = 0; p < 4; p++) {
            int row = ldrow + p * 32;
            float4 fa = *((const float4*)(A + (size_t)(m0 + row) * K + k0) + ldc4);
            float4 fb = *((const float4*)(B + (size_t)(n0 + row) * K + k0) + ldc4);
            cvt_store(fa, sAh + row * PITCH + ldc4 * 4, sAl + row * PITCH + ldc4 * 4);
            cvt_store(fb, sBh + row * PITCH + ldc4 * 4, sBl + row * PITCH + ldc4 * 4);
        }
        __syncthreads();

        #pragma unroll
        for (int ks = 0; ks < 32; ks += 16) {
            uint32_t ah[4][4], al[4][4], bh[4][2], bl[4][2];
            #pragma unroll
            for (int tm = 0; tm < 4; tm++) {
                int arow = mbase + tm * 16 + l8 + lbit * 8;
                int acol = ks + lk * 8;
                uint32_t off = (uint32_t)(arow * PITCH + acol) * 2;
                ldsm4(ah[tm], aAh + off);
                ldsm4(al[tm], aAl + off);
            }
            #pragma unroll
            for (int tn = 0; tn < 4; tn++) {
                int brow = nbase + tn * 8 + l8;
                int bcol = ks + lbit * 8;
                uint32_t off = (uint32_t)(brow * PITCH + bcol) * 2;
                ldsm2(bh[tn], aBh + off);
                ldsm2(bl[tn], aBl + off);
            }
            #pragma unroll
            for (int tm = 0; tm < 4; tm++)
                #pragma unroll
                for (int tn = 0; tn < 4; tn++) {
                    mma16816(acc[tm][tn], ah[tm], bh[tn]);
                    mma16816(acc[tm][tn], ah[tm], bl[tn]);
                    mma16816(acc[tm][tn], al[tm], bh[tn]);
                }
        }
        __syncthreads();
    }

    // Epilogue: direct float2 stores (+bias)
    #pragma unroll
    for (int tn = 0; tn < 4; tn++) {
        int gc = n0 + nbase + tn * 8 + (lid & 3) * 2;
        float bx = 0.f, by = 0.f;
        if (bias) { bx = bias[gc]; by = bias[gc + 1]; }
        #pragma unroll
        for (int tm = 0; tm < 4; tm++) {
            int gr = m0 + mbase + tm * 16 + (lid >> 2);
            float2 v0, v1;
            v0.x = acc[tm][tn][0] + bx; v0.y = acc[tm][tn][1] + by;
            v1.x = acc[tm][tn][2] + bx; v1.y = acc[tm][tn][3] + by;
            *(float2*)(C + (size_t)gr * N + gc) = v0;
            *(float2*)(C + (size_t)(gr + 8) * N + gc) = v1;
        }
    }
}

// ---------------------------------------------------------------------------
// Flash attention (causal), fp32 SIMT. 64 q-rows/block, 64-key tiles.
// P in registers; stats via half-warp shuffles; 2 CTAs/SM.
// ---------------------------------------------------------------------------
#define QPAD 132
#define ATTN_SMEM_FLOATS (3 * 64 * QPAD + 128)
#define ATTN_SMEM_BYTES  (ATTN_SMEM_FLOATS * 4)

__global__ __launch_bounds__(256, 2) void attn_kernel(
    const float* __restrict__ qkv, float* __restrict__ out)
{
    extern __shared__ float smem[];
    float* sQ = smem;
    float* sK = sQ + 64 * QPAD;
    float* sV = sK + 64 * QPAD;
    float* sM = sV + 64 * QPAD;
    float* sL = sM + 64;

    const int b   = blockIdx.y;
    const int qb  = (int)gridDim.x - 1 - (int)blockIdx.x;  // heaviest first
    const int tid = threadIdx.x;
    const int ty  = tid >> 4;
    const int tx  = tid & 15;
    const int q0  = qb * 64;
    const float* base = qkv + (size_t)b * SEQ * QKVN;

    #pragma unroll
    for (int i = tid * 4; i < 64 * DINNER; i += 256 * 4) {
        int r = i >> 7, c = i & 127;
        float4 v = *(const float4*)(base + (size_t)(q0 + r) * QKVN + c);
        v.x *= SCALE; v.y *= SCALE; v.z *= SCALE; v.w *= SCALE;
        *(float4*)&sQ[r * QPAD + c] = v;
    }
    if (tid < 64) { sM[tid] = -1e30f; sL[tid] = 0.f; }

    float oacc[4][8] = {};
    __syncthreads();

    for (int kb = 0; kb <= qb; kb++) {
        const int k0 = kb * 64;
        #pragma unroll
        for (int i = tid * 4; i < 64 * DINNER; i += 256 * 4) {
            int r = i >> 7, c = i & 127;
            const float* rowp = base + (size_t)(k0 + r) * QKVN;
            *(float4*)&sK[r * QPAD + c] = *(const float4*)(rowp + 128 + c);
            *(float4*)&sV[r * QPAD + c] = *(const float4*)(rowp + 256 + c);
        }
        __syncthreads();

        float s[4][4] = {};
        #pragma unroll 8
        for (int kk = 0; kk < 128; kk += 4) {
            float4 a[4], bb[4];
            #pragma unroll
            for (int r = 0; r < 4; r++) a[r]  = *(float4*)&sQ[(ty * 4 + r) * QPAD + kk];
            #pragma unroll
            for (int c = 0; c < 4; c++) bb[c] = *(float4*)&sK[(tx * 4 + c) * QPAD + kk];
            #pragma unroll
            for (int r = 0; r < 4; r++)
                #pragma unroll
                for (int c = 0; c < 4; c++)
                    s[r][c] += a[r].x * bb[c].x + a[r].y * bb[c].y
                             + a[r].z * bb[c].z + a[r].w * bb[c].w;
        }

        if (kb == qb) {
            #pragma unroll
            for (int r = 0; r < 4; r++)
                #pragma unroll
                for (int c = 0; c < 4; c++)
                    if ((k0 + tx * 4 + c) > (q0 + ty * 4 + r)) s[r][c] = -1e30f;
        }

        #pragma unroll
        for (int r = 0; r < 4; r++) {
            const int row = ty * 4 + r;
            float mx = fmaxf(fmaxf(s[r][0], s[r][1]), fmaxf(s[r][2], s[r][3]));
            mx = fmaxf(mx, __shfl_xor_sync(0xffffffffu, mx, 1, 16));
            mx = fmaxf(mx, __shfl_xor_sync(0xffffffffu, mx, 2, 16));
            mx = fmaxf(mx, __shfl_xor_sync(0xffffffffu, mx, 4, 16));
            mx = fmaxf(mx, __shfl_xor_sync(0xffffffffu, mx, 8, 16));
            float m_old = sM[row];
            float m_new = fmaxf(m_old, mx);
            float sum = 0.f;
            #pragma unroll
            for (int c = 0; c < 4; c++) {
                float p = __expf(s[r][c] - m_new);
                s[r][c] = p;
                sum += p;
            }
            sum += __shfl_xor_sync(0xffffffffu, sum, 1, 16);
            sum += __shfl_xor_sync(0xffffffffu, sum, 2, 16);
            sum += __shfl_xor_sync(0xffffffffu, sum, 4, 16);
            sum += __shfl_xor_sync(0xffffffffu, sum, 8, 16);
            float sc = __expf(m_old - m_new);
            if (tx == 0) { sL[row] = sL[row] * sc + sum; sM[row] = m_new; }
            #pragma unroll
            for (int c = 0; c < 8; c++) oacc[r][c] *= sc;
        }

        #pragma unroll 2
        for (int j16 = 0; j16 < 16; j16++) {
            #pragma unroll
            for (int c = 0; c < 4; c++) {
                int j = j16 * 4 + c;
                float4 va = *(float4*)&sV[j * QPAD + tx * 8];
                float4 vb = *(float4*)&sV[j * QPAD + tx * 8 + 4];
                #pragma unroll
                for (int r = 0; r < 4; r++) {
                    float pr = __shfl_sync(0xffffffffu, s[r][c], j16, 16);
                    oacc[r][0] += pr * va.x; oacc[r][1] += pr * va.y;
                    oacc[r][2] += pr * va.z; oacc[r][3] += pr * va.w;
                    oacc[r][4] += pr * vb.x; oacc[r][5] += pr * vb.y;
                    oacc[r][6] += pr * vb.z; oacc[r][7] += pr * vb.w;
                }
            }
        }
        __syncthreads();
    }

    #pragma unroll
    for (int r = 0; r < 4; r++) {
        float inv = 1.f / sL[ty * 4 + r];
        float4 va, vb;
        va.x = oacc[r][0] * inv; va.y = oacc[r][1] * inv;
        va.z = oacc[r][2] * inv; va.w = oacc[r][3] * inv;
        vb.x = oacc[r][4] * inv; vb.y = oacc[r][5] * inv;
        vb.z = oacc[r][6] * inv; vb.w = oacc[r][7] * inv;
        size_t row = (size_t)b * SEQ + q0 + ty * 4 + r;
        *(float4*)(out + row * DINNER + tx * 8)     = va;
        *(float4*)(out + row * DINNER + tx * 8 + 4) = vb;
    }
}

// ---------------------------------------------------------------------------
extern "C" void kernel_launch(void* const* d_in, const int* in_sizes, int n_in,
                              void* d_out, int out_size)
{
    const float* x     = (const float*)d_in[0];
    const float* w_qkv = (const float*)d_in[1];
    const float* w_out = (const float*)d_in[2];
    const float* b_out = (const float*)d_in[3];
    float* out = (float*)d_out;

    float *qkv_p = nullptr, *ao_p = nullptr;
    cudaGetSymbolAddress((void**)&qkv_p, g_qkv);
    cudaGetSymbolAddress((void**)&ao_p, g_ao);

    cudaFuncSetAttribute(attn_kernel, cudaFuncAttributeMaxDynamicSharedMemorySize,
                         ATTN_SMEM_BYTES);

    // 1) QKV projection: [16384,1024] x [384,1024]^T -> [16384,384]
    gemm_mma<<<dim3(QKVN / 128, M_TOTAL / 128), 256>>>(
        x, w_qkv, nullptr, qkv_p, DIN, QKVN);

    // 2) Causal flash attention -> [16384,128]
    attn_kernel<<<dim3(SEQ / 64, BATCH), 256, ATTN_SMEM_BYTES>>>(qkv_p, ao_p);

    // 3) Output projection + bias: [16384,128] x [1024,128]^T -> [16384,1024]
    gemm_mma<<<dim3(DOUT / 128, M_TOTAL / 128), 256>>>(
        ao_p, w_out, b_out, out, DINNER, DOUT);
}

// round 4
// speedup vs baseline: 7.4344x; 5.0130x over previous
#include <cuda_runtime.h>
#include <cuda_bf16.h>
#include <cuda_fp16.h>
#include <cstdint>

#define BATCH   4
#define SEQ     4096
#define DIN     1024
#define DINNER  128
#define DOUT    1024
#define QKVN    384
#define M_TOTAL (BATCH * SEQ)
#define SCALE   0.08838834764831845f

__device__ __half g_q[(size_t)M_TOTAL * DINNER];
__device__ __half g_k[(size_t)M_TOTAL * DINNER];
__device__ __half g_v[(size_t)M_TOTAL * DINNER];
__device__ float  g_ao[(size_t)M_TOTAL * DINNER];

// ---------------------------------------------------------------------------
// Helpers (generic PTX: ldmatrix sm_75+, mma.sync sm_80+)
// ---------------------------------------------------------------------------
__device__ __forceinline__ uint32_t smem_u32(const void* p) {
    uint32_t a;
    asm("{ .reg .u64 t; cvta.to.shared.u64 t, %1; cvt.u32.u64 %0, t; }"
        : "=r"(a) : "l"(p));
    return a;
}
__device__ __forceinline__ void ldsm4(uint32_t* r, uint32_t a) {
    asm volatile("ldmatrix.sync.aligned.m8n8.x4.shared.b16 {%0,%1,%2,%3}, [%4];"
        : "=r"(r[0]), "=r"(r[1]), "=r"(r[2]), "=r"(r[3]) : "r"(a));
}
__device__ __forceinline__ void ldsm4t(uint32_t* r, uint32_t a) {
    asm volatile("ldmatrix.sync.aligned.m8n8.x4.trans.shared.b16 {%0,%1,%2,%3}, [%4];"
        : "=r"(r[0]), "=r"(r[1]), "=r"(r[2]), "=r"(r[3]) : "r"(a));
}
__device__ __forceinline__ void ldsm2(uint32_t* r, uint32_t a) {
    asm volatile("ldmatrix.sync.aligned.m8n8.x2.shared.b16 {%0,%1}, [%2];"
        : "=r"(r[0]), "=r"(r[1]) : "r"(a));
}
__device__ __forceinline__ void mma_bf16(float* c, const uint32_t* a,
                                         const uint32_t* b) {
    asm volatile(
        "mma.sync.aligned.m16n8k16.row.col.f32.bf16.bf16.f32 "
        "{%0,%1,%2,%3}, {%4,%5,%6,%7}, {%8,%9}, {%0,%1,%2,%3};"
        : "+f"(c[0]), "+f"(c[1]), "+f"(c[2]), "+f"(c[3])
        : "r"(a[0]), "r"(a[1]), "r"(a[2]), "r"(a[3]), "r"(b[0]), "r"(b[1]));
}
__device__ __forceinline__ void mma_f16(float* c, const uint32_t* a,
                                        const uint32_t* b) {
    asm volatile(
        "mma.sync.aligned.m16n8k16.row.col.f32.f16.f16.f32 "
        "{%0,%1,%2,%3}, {%4,%5,%6,%7}, {%8,%9}, {%0,%1,%2,%3};"
        : "+f"(c[0]), "+f"(c[1]), "+f"(c[2]), "+f"(c[3])
        : "r"(a[0]), "r"(a[1]), "r"(a[2]), "r"(a[3]), "r"(b[0]), "r"(b[1]));
}
__device__ __forceinline__ void cvt_store(float4 f, __nv_bfloat16* hp,
                                          __nv_bfloat16* lp) {
    __nv_bfloat162 h01 = __floats2bfloat162_rn(f.x, f.y);
    __nv_bfloat162 h23 = __floats2bfloat162_rn(f.z, f.w);
    float lx = f.x - __bfloat162float(h01.x);
    float ly = f.y - __bfloat162float(h01.y);
    float lz = f.z - __bfloat162float(h23.x);
    float lw = f.w - __bfloat162float(h23.y);
    __nv_bfloat162 l01 = __floats2bfloat162_rn(lx, ly);
    __nv_bfloat162 l23 = __floats2bfloat162_rn(lz, lw);
    uint2 hv, lv;
    hv.x = *(uint32_t*)&h01; hv.y = *(uint32_t*)&h23;
    lv.x = *(uint32_t*)&l01; lv.y = *(uint32_t*)&l23;
    *(uint2*)hp = hv;
    *(uint2*)lp = lv;
}
__device__ __forceinline__ uint32_t packh2(float a, float b) {
    __half2 h = __floats2half2_rn(a, b);
    return *(uint32_t*)&h;
}

// ---------------------------------------------------------------------------
// QKV GEMM (bf16x3 split precision), epilogue writes fp16 Q(scaled)/K/V.
// Block 128x128x32, 8 warps.
// ---------------------------------------------------------------------------
#define PITCH 40

__global__ __launch_bounds__(256) void gemm_qkv(
    const float* __restrict__ A, const float* __restrict__ B)
{
    __shared__ __nv_bfloat16 sAh[128 * PITCH], sAl[128 * PITCH];
    __shared__ __nv_bfloat16 sBh[128 * PITCH], sBl[128 * PITCH];

    const int tid = threadIdx.x;
    const int lid = tid & 31, wid = tid >> 5;
    const int m0 = blockIdx.y * 128, n0 = blockIdx.x * 128;
    const int mbase = (wid & 1) * 64, nbase = (wid >> 1) * 32;
    const uint32_t aAh = smem_u32(sAh), aAl = smem_u32(sAl);
    const uint32_t aBh = smem_u32(sBh), aBl = smem_u32(sBl);
    const int l8 = lid & 7, lbit = (lid >> 3) & 1, lk = lid >> 4;
    const int ldrow = tid >> 3, ldc4 = tid & 7;
    const int K = DIN;

    float acc[4][4][4] = {};

    for (int k0 = 0; k0 < K; k0 += 32) {
        #pragma unroll
        for (int p = 0; p < 4; p++) {
            int row = ldrow + p * 32;
            float4 fa = *((const float4*)(A + (size_t)(m0 + row) * K + k0) + ldc4);
            float4 fb = *((const float4*)(B + (size_t)(n0 + row) * K + k0) + ldc4);
            cvt_store(fa, sAh + row * PITCH + ldc4 * 4, sAl + row * PITCH + ldc4 * 4);
            cvt_store(fb, sBh + row * PITCH + ldc4 * 4, sBl + row * PITCH + ldc4 * 4);
        }
        __syncthreads();
        #pragma unroll
        for (int ks = 0; ks < 32; ks += 16) {
            uint32_t ah[4][4], al[4][4], bh[4][2], bl[4][2];
            #pragma unroll
            for (int tm = 0; tm < 4; tm++) {
                uint32_t off = (uint32_t)((mbase + tm * 16 + l8 + lbit * 8) * PITCH
                                          + ks + lk * 8) * 2;
                ldsm4(ah[tm], aAh + off);
                ldsm4(al[tm], aAl + off);
            }
            #pragma unroll
            for (int tn = 0; tn < 4; tn++) {
                uint32_t off = (uint32_t)((nbase + tn * 8 + l8) * PITCH
                                          + ks + lbit * 8) * 2;
                ldsm2(bh[tn], aBh + off);
                ldsm2(bl[tn], aBl + off);
            }
            #pragma unroll
            for (int tm = 0; tm < 4; tm++)
                #pragma unroll
                for (int tn = 0; tn < 4; tn++) {
                    mma_bf16(acc[tm][tn], ah[tm], bh[tn]);
                    mma_bf16(acc[tm][tn], ah[tm], bl[tn]);
                    mma_bf16(acc[tm][tn], al[tm], bh[tn]);
                }
        }
        __syncthreads();
    }

    // Epilogue: region 0 -> Q (scaled), 1 -> K, 2 -> V, fp16.
    __half* dst = (blockIdx.x == 0) ? g_q : (blockIdx.x == 1 ? g_k : g_v);
    const float scl = (blockIdx.x == 0) ? SCALE : 1.0f;
    #pragma unroll
    for (int tn = 0; tn < 4; tn++) {
        int gc = nbase + tn * 8 + (lid & 3) * 2;
        #pragma unroll
        for (int tm = 0; tm < 4; tm++) {
            int gr = m0 + mbase + tm * 16 + (lid >> 2);
            __half2 h0 = __floats2half2_rn(acc[tm][tn][0] * scl, acc[tm][tn][1] * scl);
            __half2 h1 = __floats2half2_rn(acc[tm][tn][2] * scl, acc[tm][tn][3] * scl);
            *(__half2*)(dst + (size_t)gr * DINNER + gc) = h0;
            *(__half2*)(dst + (size_t)(gr + 8) * DINNER + gc) = h1;
        }
    }
}

// ---------------------------------------------------------------------------
// Out-projection GEMM (bf16x3), fp32 out + bias. Same structure as R3.
// ---------------------------------------------------------------------------
__global__ __launch_bounds__(256) void gemm_out(
    const float* __restrict__ A, const float* __restrict__ B,
    const float* __restrict__ bias, float* __restrict__ C,
    int K, int N)
{
    __shared__ __nv_bfloat16 sAh[128 * PITCH], sAl[128 * PITCH];
    __shared__ __nv_bfloat16 sBh[128 * PITCH], sBl[128 * PITCH];

    const int tid = threadIdx.x;
    const int lid = tid & 31, wid = tid >> 5;
    const int m0 = blockIdx.y * 128, n0 = blockIdx.x * 128;
    const int mbase = (wid & 1) * 64, nbase = (wid >> 1) * 32;
    const uint32_t aAh = smem_u32(sAh), aAl = smem_u32(sAl);
    const uint32_t aBh = smem_u32(sBh), aBl = smem_u32(sBl);
    const int l8 = lid & 7, lbit = (lid >> 3) & 1, lk = lid >> 4;
    const int ldrow = tid >> 3, ldc4 = tid & 7;

    float acc[4][4][4] = {};

    for (int k0 = 0; k0 < K; k0 += 32) {
        #pragma unroll
        for (int p = 0; p < 4; p++) {
            int row = ldrow + p * 32;
            float4 fa = *((const float4*)(A + (size_t)(m0 + row) * K + k0) + ldc4);
            float4 fb = *((const float4*)(B + (size_t)(n0 + row) * K + k0) + ldc4);
            cvt_store(fa, sAh + row * PITCH + ldc4 * 4, sAl + row * PITCH + ldc4 * 4);
            cvt_store(fb, sBh + row * PITCH + ldc4 * 4, sBl + row * PITCH + ldc4 * 4);
        }
        __syncthreads();
        #pragma unroll
        for (int ks = 0; ks < 32; ks += 16) {
            uint32_t ah[4][4], al[4][4], bh[4][2], bl[4][2];
            #pragma unroll
            for (int tm = 0; tm < 4; tm++) {
                uint32_t off = (uint32_t)((mbase + tm * 16 + l8 + lbit * 8) * PITCH
                                          + ks + lk * 8) * 2;
                ldsm4(ah[tm], aAh + off);
                ldsm4(al[tm], aAl + off);
            }
            #pragma unroll
            for (int tn = 0; tn < 4; tn++) {
                uint32_t off = (uint32_t)((nbase + tn * 8 + l8) * PITCH
                                          + ks + lbit * 8) * 2;
                ldsm2(bh[tn], aBh + off);
                ldsm2(bl[tn], aBl + off);
            }
            #pragma unroll
            for (int tm = 0; tm < 4; tm++)
                #pragma unroll
                for (int tn = 0; tn < 4; tn++) {
                    mma_bf16(acc[tm][tn], ah[tm], bh[tn]);
                    mma_bf16(acc[tm][tn], ah[tm], bl[tn]);
                    mma_bf16(acc[tm][tn], al[tm], bh[tn]);
                }
        }
        __syncthreads();
    }

    #pragma unroll
    for (int tn = 0; tn < 4; tn++) {
        int gc = n0 + nbase + tn * 8 + (lid & 3) * 2;
        float bx = bias[gc], by = bias[gc + 1];
        #pragma unroll
        for (int tm = 0; tm < 4; tm++) {
            int gr = m0 + mbase + tm * 16 + (lid >> 2);
            float2 v0, v1;
            v0.x = acc[tm][tn][0] + bx; v0.y = acc[tm][tn][1] + by;
            v1.x = acc[tm][tn][2] + bx; v1.y = acc[tm][tn][3] + by;
            *(float2*)(C + (size_t)gr * N + gc) = v0;
            *(float2*)(C + (size_t)(gr + 8) * N + gc) = v1;
        }
    }
}

// ---------------------------------------------------------------------------
// Flash attention (causal) on mma.sync fp16.
// CTA: 128 threads (4 warps), 64 q-rows; 64-key tiles; d=128.
// Q frags cached in regs; P kept in regs (FA2 accumulator->A-operand reuse).
// ---------------------------------------------------------------------------
#define AP 136   // fp16 pitch: 272B rows -> 4-bank shift, conflict-free ldmatrix
#define ATTN_SMEM (3 * 64 * AP * 2)

__global__ __launch_bounds__(128, 2) void attn_mma(
    const __half* __restrict__ gq, const __half* __restrict__ gk,
    const __half* __restrict__ gv, float* __restrict__ out)
{
    extern __shared__ __half sm[];
    __half* sQ = sm;
    __half* sK = sQ + 64 * AP;
    __half* sV = sK + 64 * AP;

    const int b   = blockIdx.y;
    const int qb  = (int)gridDim.x - 1 - (int)blockIdx.x;  // heaviest first
    const int tid = threadIdx.x, lid = tid & 31, w = tid >> 5;
    const int q0  = qb * 64;
    const int l8  = lid & 7, lbit = (lid >> 3) & 1, lk = lid >> 4;
    const int lq  = lid >> 2, lc = lid & 3;
    const size_t rowbase = (size_t)b * SEQ;

    // Load Q tile (fp16, pre-scaled)
    #pragma unroll
    for (int i = 0; i < 8; i++) {
        int idx = i * 128 + tid;
        int r = idx >> 4, c = idx & 15;
        *(uint4*)(sQ + r * AP + c * 8) =
            *(const uint4*)(gq + (rowbase + q0 + r) * DINNER + c * 8);
    }
    __syncthreads();

    // Cache Q fragments (16 rows per warp x d=128)
    uint32_t qf[8][4];
    {
        const uint32_t bQ = smem_u32(sQ);
        const int arow = w * 16 + l8 + lbit * 8;
        #pragma unroll
        for (int ks = 0; ks < 8; ks++)
            ldsm4(qf[ks], bQ + (uint32_t)(arow * AP + ks * 16 + lk * 8) * 2);
    }

    float o[16][4] = {};
    float m0 = -1e30f, m1 = -1e30f, l0 = 0.f, l1 = 0.f;
    const uint32_t bK = smem_u32(sK), bV = smem_u32(sV);

    for (int kb = 0; kb <= qb; kb++) {
        __syncthreads();
        const int k0 = kb * 64;
        #pragma unroll
        for (int i = 0; i < 8; i++) {
            int idx = i * 128 + tid;
            int r = idx >> 4, c = idx & 15;
            *(uint4*)(sK + r * AP + c * 8) =
                *(const uint4*)(gk + (rowbase + k0 + r) * DINNER + c * 8);
            *(uint4*)(sV + r * AP + c * 8) =
                *(const uint4*)(gv + (rowbase + k0 + r) * DINNER + c * 8);
        }
        __syncthreads();

        // S = Q K^T : 8 n-tiles (64 keys), 8 k16-steps (d=128)
        float s[8][4] = {};
        #pragma unroll
        for (int ks = 0; ks < 8; ks++) {
            #pragma unroll
            for (int tp = 0; tp < 4; tp++) {
                uint32_t bf[4];
                ldsm4(bf, bK + (uint32_t)((tp * 16 + l8 + lk * 8) * AP
                                          + ks * 16 + lbit * 8) * 2);
                mma_f16(s[2 * tp],     qf[ks], bf);
                mma_f16(s[2 * tp + 1], qf[ks], bf + 2);
            }
        }

        // Causal mask on diagonal tile
        if (kb == qb) {
            const int r0 = w * 16 + lq, r1 = r0 + 8;
            #pragma unroll
            for (int t = 0; t < 8; t++) {
                int c0 = t * 8 + lc * 2;
                if (c0 > r0)     s[t][0] = -1e30f;
                if (c0 + 1 > r0) s[t][1] = -1e30f;
                if (c0 > r1)     s[t][2] = -1e30f;
                if (c0 + 1 > r1) s[t][3] = -1e30f;
            }
        }

        // Online softmax (per-thread rows lq and lq+8; quad reductions)
        float mx0 = -1e30f, mx1 = -1e30f;
        #pragma unroll
        for (int t = 0; t < 8; t++) {
            mx0 = fmaxf(mx0, fmaxf(s[t][0], s[t][1]));
            mx1 = fmaxf(mx1, fmaxf(s[t][2], s[t][3]));
        }
        mx0 = fmaxf(mx0, __shfl_xor_sync(~0u, mx0, 1));
        mx0 = fmaxf(mx0, __shfl_xor_sync(~0u, mx0, 2));
        mx1 = fmaxf(mx1, __shfl_xor_sync(~0u, mx1, 1));
        mx1 = fmaxf(mx1, __shfl_xor_sync(~0u, mx1, 2));
        float mn0 = fmaxf(m0, mx0), mn1 = fmaxf(m1, mx1);
        float sc0 = __expf(m0 - mn0), sc1 = __expf(m1 - mn1);
        float sum0 = 0.f, sum1 = 0.f;
        #pragma unroll
        for (int t = 0; t < 8; t++) {
            s[t][0] = __expf(s[t][0] - mn0);
            s[t][1] = __expf(s[t][1] - mn0);
            s[t][2] = __expf(s[t][2] - mn1);
            s[t][3] = __expf(s[t][3] - mn1);
            sum0 += s[t][0] + s[t][1];
            sum1 += s[t][2] + s[t][3];
        }
        sum0 += __shfl_xor_sync(~0u, sum0, 1);
        sum0 += __shfl_xor_sync(~0u, sum0, 2);
        sum1 += __shfl_xor_sync(~0u, sum1, 1);
        sum1 += __shfl_xor_sync(~0u, sum1, 2);
        l0 = l0 * sc0 + sum0;  l1 = l1 * sc1 + sum1;
        m0 = mn0;  m1 = mn1;
        #pragma unroll
        for (int t = 0; t < 16; t++) {
            o[t][0] *= sc0; o[t][1] *= sc0;
            o[t][2] *= sc1; o[t][3] *= sc1;
        }

        // Pack P -> fp16 A-fragments (accumulator layout reuse)
        uint32_t pa[4][4];
        #pragma unroll
        for (int c = 0; c < 4; c++) {
            pa[c][0] = packh2(s[2 * c][0],     s[2 * c][1]);
            pa[c][1] = packh2(s[2 * c][2],     s[2 * c][3]);
            pa[c][2] = packh2(s[2 * c + 1][0], s[2 * c + 1][1]);
            pa[c][3] = packh2(s[2 * c + 1][2], s[2 * c + 1][3]);
        }

        // O += P @ V : 4 k16-chunks (keys), 16 d-tiles via trans ldmatrix
        #pragma unroll
        for (int c = 0; c < 4; c++) {
            #pragma unroll
            for (int dp = 0; dp < 8; dp++) {
                uint32_t vf[4];
                ldsm4t(vf, bV + (uint32_t)((c * 16 + l8 + lbit * 8) * AP
                                           + dp * 16 + lk * 8) * 2);
                mma_f16(o[2 * dp],     pa[c], vf);
                mma_f16(o[2 * dp + 1], pa[c], vf + 2);
            }
        }
    }

    // Normalize and store
    const float inv0 = 1.f / l0, inv1 = 1.f / l1;
    const size_t gr0 = rowbase + q0 + w * 16 + lq;
    #pragma unroll
    for (int t = 0; t < 16; t++) {
        int col = t * 8 + lc * 2;
        float2 v0, v1;
        v0.x = o[t][0] * inv0; v0.y = o[t][1] * inv0;
        v1.x = o[t][2] * inv1; v1.y = o[t][3] * inv1;
        *(float2*)(out + gr0 * DINNER + col) = v0;
        *(float2*)(out + (gr0 + 8) * DINNER + col) = v1;
    }
}

// ---------------------------------------------------------------------------
extern "C" void kernel_launch(void* const* d_in, const int* in_sizes, int n_in,
                              void* d_out, int out_size)
{
    const float* x     = (const float*)d_in[0];
    const float* w_qkv = (const float*)d_in[1];
    const float* w_out = (const float*)d_in[2];
    const float* b_out = (const float*)d_in[3];
    float* out = (float*)d_out;

    __half *q_p = nullptr, *k_p = nullptr, *v_p = nullptr;
    float* ao_p = nullptr;
    cudaGetSymbolAddress((void**)&q_p, g_q);
    cudaGetSymbolAddress((void**)&k_p, g_k);
    cudaGetSymbolAddress((void**)&v_p, g_v);
    cudaGetSymbolAddress((void**)&ao_p, g_ao);

    cudaFuncSetAttribute(attn_mma, cudaFuncAttributeMaxDynamicSharedMemorySize,
                         ATTN_SMEM);

    // 1) QKV projection -> fp16 Q(scaled)/K/V
    gemm_qkv<<<dim3(QKVN / 128, M_TOTAL / 128), 256>>>(x, w_qkv);

    // 2) Causal flash attention (tensor core) -> fp32 [16384,128]
    attn_mma<<<dim3(SEQ / 64, BATCH), 128, ATTN_SMEM>>>(q_p, k_p, v_p, ao_p);

    // 3) Output projection + bias
    gemm_out<<<dim3(DOUT / 128, M_TOTAL / 128), 256>>>(
        ao_p, w_out, b_out, out, DINNER, DOUT);
}

// round 5
// speedup vs baseline: 8.8144x; 1.1856x over previous
#include <cuda_runtime.h>
#include <cuda_bf16.h>
#include <cuda_fp16.h>
#include <cstdint>

#define BATCH   4
#define SEQ     4096
#define DIN     1024
#define DINNER  128
#define DOUT    1024
#define QKVN    384
#define M_TOTAL (BATCH * SEQ)
#define SCALE   0.08838834764831845f

// Scratch
__device__ __nv_bfloat16 g_xh[(size_t)M_TOTAL * DIN];
__device__ __nv_bfloat16 g_xl[(size_t)M_TOTAL * DIN];
__device__ __nv_bfloat16 g_wqh[QKVN * DIN];
__device__ __nv_bfloat16 g_wql[QKVN * DIN];
__device__ __nv_bfloat16 g_woh[DOUT * DINNER];
__device__ __nv_bfloat16 g_wol[DOUT * DINNER];
__device__ __half g_q[(size_t)M_TOTAL * DINNER];
__device__ __half g_k[(size_t)M_TOTAL * DINNER];
__device__ __half g_v[(size_t)M_TOTAL * DINNER];
__device__ __nv_bfloat16 g_aoh[(size_t)M_TOTAL * DINNER];
__device__ __nv_bfloat16 g_aol[(size_t)M_TOTAL * DINNER];
__device__ float g_po[(size_t)BATCH * 64 * 4 * 64 * DINNER];
__device__ float g_pm[BATCH * 64 * 4 * 64];
__device__ float g_pl[BATCH * 64 * 4 * 64];

// ---------------------------------------------------------------------------
// PTX helpers
// ---------------------------------------------------------------------------
__device__ __forceinline__ uint32_t smem_u32(const void* p) {
    uint32_t a;
    asm("{ .reg .u64 t; cvta.to.shared.u64 t, %1; cvt.u32.u64 %0, t; }"
        : "=r"(a) : "l"(p));
    return a;
}
__device__ __forceinline__ void cpa16(uint32_t dst, const void* src) {
    asm volatile("cp.async.cg.shared.global [%0], [%1], 16;"
                 :: "r"(dst), "l"(src));
}
__device__ __forceinline__ void cp_commit() {
    asm volatile("cp.async.commit_group;" ::: "memory");
}
__device__ __forceinline__ void cp_wait1() {
    asm volatile("cp.async.wait_group 1;" ::: "memory");
}
__device__ __forceinline__ void cp_wait0() {
    asm volatile("cp.async.wait_group 0;" ::: "memory");
}
__device__ __forceinline__ void ldsm4(uint32_t* r, uint32_t a) {
    asm volatile("ldmatrix.sync.aligned.m8n8.x4.shared.b16 {%0,%1,%2,%3}, [%4];"
        : "=r"(r[0]), "=r"(r[1]), "=r"(r[2]), "=r"(r[3]) : "r"(a));
}
__device__ __forceinline__ void ldsm4t(uint32_t* r, uint32_t a) {
    asm volatile("ldmatrix.sync.aligned.m8n8.x4.trans.shared.b16 {%0,%1,%2,%3}, [%4];"
        : "=r"(r[0]), "=r"(r[1]), "=r"(r[2]), "=r"(r[3]) : "r"(a));
}
__device__ __forceinline__ void ldsm2(uint32_t* r, uint32_t a) {
    asm volatile("ldmatrix.sync.aligned.m8n8.x2.shared.b16 {%0,%1}, [%2];"
        : "=r"(r[0]), "=r"(r[1]) : "r"(a));
}
__device__ __forceinline__ void mma_bf16(float* c, const uint32_t* a,
                                         const uint32_t* b) {
    asm volatile(
        "mma.sync.aligned.m16n8k16.row.col.f32.bf16.bf16.f32 "
        "{%0,%1,%2,%3}, {%4,%5,%6,%7}, {%8,%9}, {%0,%1,%2,%3};"
        : "+f"(c[0]), "+f"(c[1]), "+f"(c[2]), "+f"(c[3])
        : "r"(a[0]), "r"(a[1]), "r"(a[2]), "r"(a[3]), "r"(b[0]), "r"(b[1]));
}
__device__ __forceinline__ void mma_f16(float* c, const uint32_t* a,
                                        const uint32_t* b) {
    asm volatile(
        "mma.sync.aligned.m16n8k16.row.col.f32.f16.f16.f32 "
        "{%0,%1,%2,%3}, {%4,%5,%6,%7}, {%8,%9}, {%0,%1,%2,%3};"
        : "+f"(c[0]), "+f"(c[1]), "+f"(c[2]), "+f"(c[3])
        : "r"(a[0]), "r"(a[1]), "r"(a[2]), "r"(a[3]), "r"(b[0]), "r"(b[1]));
}
__device__ __forceinline__ uint32_t packh2(float a, float b) {
    __half2 h = __floats2half2_rn(a, b);
    return *(uint32_t*)&h;
}
__device__ __forceinline__ void store_hilo2(float x, float y,
                                            __nv_bfloat16* hp, __nv_bfloat16* lp) {
    __nv_bfloat162 h = __floats2bfloat162_rn(x, y);
    float lx = x - __bfloat162float(h.x);
    float ly = y - __bfloat162float(h.y);
    __nv_bfloat162 l = __floats2bfloat162_rn(lx, ly);
    *(__nv_bfloat162*)hp = h;
    *(__nv_bfloat162*)lp = l;
}

// ---------------------------------------------------------------------------
// fp32 -> bf16 hi/lo split (elementwise)
// ---------------------------------------------------------------------------
__global__ __launch_bounds__(256) void split_fp32(
    const float* __restrict__ src, __nv_bfloat16* __restrict__ hi,
    __nv_bfloat16* __restrict__ lo, int n4)
{
    int i = blockIdx.x * 256 + threadIdx.x;
    if (i >= n4) return;
    float4 f = ((const float4*)src)[i];
    store_hilo2(f.x, f.y, hi + i * 4, lo + i * 4);
    store_hilo2(f.z, f.w, hi + i * 4 + 2, lo + i * 4 + 2);
}

// ---------------------------------------------------------------------------
// bf16x3 GEMM with cp.async double-buffering. Tile 128x128x32, 256 threads.
// Operands pre-split: C[m,n] = Ah*Bh + Ah*Bl + Al*Bh (A:[M,K], B:[N,K]).
// ---------------------------------------------------------------------------
#define PITCH 40
#define ARR_B 10240          // one 128x40 bf16 array
#define STG_B (4 * ARR_B)    // one stage: Ah, Al, Bh, Bl
#define GEMM_SMEM (2 * STG_B)

struct GemmFrag { float acc[4][4][4]; };

__device__ __forceinline__ void gemm_issue(
    const __nv_bfloat16* Ah, const __nv_bfloat16* Al,
    const __nv_bfloat16* Bh, const __nv_bfloat16* Bl,
    int K, int m0, int n0, int k0, uint32_t stage_base, int tid)
{
    const int row = tid >> 2, col = tid & 3;
    const uint32_t doff1 = (uint32_t)(row * PITCH + col * 8) * 2;
    const uint32_t doff2 = (uint32_t)((row + 64) * PITCH + col * 8) * 2;
    const size_t sa1 = (size_t)(m0 + row) * K + k0 + col * 8;
    const size_t sa2 = (size_t)(m0 + row + 64) * K + k0 + col * 8;
    const size_t sb1 = (size_t)(n0 + row) * K + k0 + col * 8;
    const size_t sb2 = (size_t)(n0 + row + 64) * K + k0 + col * 8;
    cpa16(stage_base + doff1,              Ah + sa1);
    cpa16(stage_base + doff2,              Ah + sa2);
    cpa16(stage_base + ARR_B + doff1,      Al + sa1);
    cpa16(stage_base + ARR_B + doff2,      Al + sa2);
    cpa16(stage_base + 2 * ARR_B + doff1,  Bh + sb1);
    cpa16(stage_base + 2 * ARR_B + doff2,  Bh + sb2);
    cpa16(stage_base + 3 * ARR_B + doff1,  Bl + sb1);
    cpa16(stage_base + 3 * ARR_B + doff2,  Bl + sb2);
    cp_commit();
}

__device__ __forceinline__ void gemm_mainloop(
    GemmFrag& fr,
    const __nv_bfloat16* Ah, const __nv_bfloat16* Al,
    const __nv_bfloat16* Bh, const __nv_bfloat16* Bl,
    int K, int m0, int n0, uint32_t sb, int tid)
{
    const int lid = tid & 31, wid = tid >> 5;
    const int mbase = (wid & 1) * 64, nbase = (wid >> 1) * 32;
    const int l8 = lid & 7, lbit = (lid >> 3) & 1, lk = lid >> 4;
    const int nk = K >> 5;

    gemm_issue(Ah, Al, Bh, Bl, K, m0, n0, 0, sb, tid);

    for (int it = 0; it < nk; it++) {
        if (it + 1 < nk)
            gemm_issue(Ah, Al, Bh, Bl, K, m0, n0, (it + 1) << 5,
                       sb + ((it + 1) & 1) * STG_B, tid);
        if (it + 1 < nk) cp_wait1(); else cp_wait0();
        __syncthreads();

        const uint32_t base = sb + (it & 1) * STG_B;
        const uint32_t aAh = base, aAl = base + ARR_B;
        const uint32_t aBh = base + 2 * ARR_B, aBl = base + 3 * ARR_B;

        #pragma unroll
        for (int ks = 0; ks < 32; ks += 16) {
            uint32_t ah[4][4], al[4][4], bh[4][2], bl[4][2];
            #pragma unroll
            for (int tm = 0; tm < 4; tm++) {
                uint32_t off = (uint32_t)((mbase + tm * 16 + l8 + lbit * 8) * PITCH
                                          + ks + lk * 8) * 2;
                ldsm4(ah[tm], aAh + off);
                ldsm4(al[tm], aAl + off);
            }
            #pragma unroll
            for (int tn = 0; tn < 4; tn++) {
                uint32_t off = (uint32_t)((nbase + tn * 8 + l8) * PITCH
                                          + ks + lbit * 8) * 2;
                ldsm2(bh[tn], aBh + off);
                ldsm2(bl[tn], aBl + off);
            }
            #pragma unroll
            for (int tm = 0; tm < 4; tm++)
                #pragma unroll
                for (int tn = 0; tn < 4; tn++) {
                    mma_bf16(fr.acc[tm][tn], ah[tm], bh[tn]);
                    mma_bf16(fr.acc[tm][tn], ah[tm], bl[tn]);
                    mma_bf16(fr.acc[tm][tn], al[tm], bh[tn]);
                }
        }
        __syncthreads();
    }
}

// QKV GEMM: epilogue writes fp16 q(scaled)/k/v
__global__ __launch_bounds__(256, 2) void gemm_qkv(
    const __nv_bfloat16* __restrict__ Ah, const __nv_bfloat16* __restrict__ Al,
    const __nv_bfloat16* __restrict__ Bh, const __nv_bfloat16* __restrict__ Bl)
{
    extern __shared__ char smc[];
    const uint32_t sb = smem_u32(smc);
    const int tid = threadIdx.x, lid = tid & 31, wid = tid >> 5;
    const int m0 = blockIdx.y * 128, n0 = blockIdx.x * 128;
    const int mbase = (wid & 1) * 64, nbase = (wid >> 1) * 32;

    GemmFrag fr = {};
    gemm_mainloop(fr, Ah, Al, Bh, Bl, DIN, m0, n0, sb, tid);

    __half* dst = (blockIdx.x == 0) ? g_q : (blockIdx.x == 1 ? g_k : g_v);
    const float scl = (blockIdx.x == 0) ? SCALE : 1.0f;
    #pragma unroll
    for (int tn = 0; tn < 4; tn++) {
        int gc = nbase + tn * 8 + (lid & 3) * 2;
        #pragma unroll
        for (int tm = 0; tm < 4; tm++) {
            int gr = m0 + mbase + tm * 16 + (lid >> 2);
            __half2 h0 = __floats2half2_rn(fr.acc[tm][tn][0] * scl,
                                           fr.acc[tm][tn][1] * scl);
            __half2 h1 = __floats2half2_rn(fr.acc[tm][tn][2] * scl,
                                           fr.acc[tm][tn][3] * scl);
            *(__half2*)(dst + (size_t)gr * DINNER + gc) = h0;
            *(__half2*)(dst + (size_t)(gr + 8) * DINNER + gc) = h1;
        }
    }
}

// Out GEMM: fp32 + bias
__global__ __launch_bounds__(256, 2) void gemm_out(
    const __nv_bfloat16* __restrict__ Ah, const __nv_bfloat16* __restrict__ Al,
    const __nv_bfloat16* __restrict__ Bh, const __nv_bfloat16* __restrict__ Bl,
    const float* __restrict__ bias, float* __restrict__ C)
{
    extern __shared__ char smc[];
    const uint32_t sb = smem_u32(smc);
    const int tid = threadIdx.x, lid = tid & 31, wid = tid >> 5;
    const int m0 = blockIdx.y * 128, n0 = blockIdx.x * 128;
    const int mbase = (wid & 1) * 64, nbase = (wid >> 1) * 32;

    GemmFrag fr = {};
    gemm_mainloop(fr, Ah, Al, Bh, Bl, DINNER, m0, n0, sb, tid);

    #pragma unroll
    for (int tn = 0; tn < 4; tn++) {
        int gc = n0 + nbase + tn * 8 + (lid & 3) * 2;
        float bx = bias[gc], by = bias[gc + 1];
        #pragma unroll
        for (int tm = 0; tm < 4; tm++) {
            int gr = m0 + mbase + tm * 16 + (lid >> 2);
            float2 v0, v1;
            v0.x = fr.acc[tm][tn][0] + bx; v0.y = fr.acc[tm][tn][1] + by;
            v1.x = fr.acc[tm][tn][2] + bx; v1.y = fr.acc[tm][tn][3] + by;
            *(float2*)(C + (size_t)gr * DOUT + gc) = v0;
            *(float2*)(C + (size_t)(gr + 8) * DOUT + gc) = v1;
        }
    }
}

// ---------------------------------------------------------------------------
// Split-K flash attention (causal), mma.sync fp16.
// Grid (64 qtiles, 4 splits, 4 batch); split covers 16 key-tiles (1024 keys).
// cp.async double-buffered K/V. Single-split tiles write bf16 hi/lo output;
// multi-split tiles write fp32 partials merged by attn_combine.
// ---------------------------------------------------------------------------
#define AP 136
#define Q_BYTES  (64 * AP * 2)        // 17408
#define KV_STAGE (2 * Q_BYTES)        // 34816
#define ATTN_SMEM (Q_BYTES + 2 * KV_STAGE)

__global__ __launch_bounds__(128, 2) void attn_part(
    const __half* __restrict__ gq, const __half* __restrict__ gk,
    const __half* __restrict__ gv,
    __nv_bfloat16* __restrict__ aoh, __nv_bfloat16* __restrict__ aol,
    float* __restrict__ po, float* __restrict__ pm, float* __restrict__ pl)
{
    extern __shared__ char smc[];
    const int qb = blockIdx.x, sp = blockIdx.y, b = blockIdx.z;
    const int ntiles = qb + 1;
    const int kb0 = sp * 16;
    if (kb0 >= ntiles) return;
    const int kbend = (kb0 + 16 < ntiles) ? (kb0 + 16) : ntiles;
    const int nsplit = (qb >> 4) + 1;

    const int tid = threadIdx.x, lid = tid & 31, w = tid >> 5;
    const int q0 = qb * 64;
    const int l8 = lid & 7, lbit = (lid >> 3) & 1, lk = lid >> 4;
    const int lq = lid >> 2, lc = lid & 3;
    const size_t rowbase = (size_t)b * SEQ;
    const uint32_t sb = smem_u32(smc);
    __half* sQ = (__half*)smc;

    const int r0c = tid >> 4, cc = tid & 15;

    // issue K/V tile kb into stage st
    auto issueKV = [&](int kb, int st) {
        const __half* srcK = gk + (rowbase + (size_t)kb * 64) * DINNER;
        const __half* srcV = gv + (rowbase + (size_t)kb * 64) * DINNER;
        uint32_t dK = sb + Q_BYTES + st * KV_STAGE;
        uint32_t dV = dK + Q_BYTES;
        #pragma unroll
        for (int j = 0; j < 8; j++) {
            int row = r0c + j * 8;
            uint32_t doff = (uint32_t)(row * AP + cc * 8) * 2;
            cpa16(dK + doff, srcK + row * DINNER + cc * 8);
            cpa16(dV + doff, srcV + row * DINNER + cc * 8);
        }
        cp_commit();
    };

    issueKV(kb0, 0);

    // Load Q (regular loads)
    #pragma unroll
    for (int i = 0; i < 8; i++) {
        int idx = i * 128 + tid;
        int r = idx >> 4, c = idx & 15;
        *(uint4*)(sQ + r * AP + c * 8) =
            *(const uint4*)(gq + (rowbase + q0 + r) * DINNER + c * 8);
    }
    __syncthreads();

    uint32_t qf[8][4];
    {
        const int arow = w * 16 + l8 + lbit * 8;
        #pragma unroll
        for (int ks = 0; ks < 8; ks++)
            ldsm4(qf[ks], sb + (uint32_t)(arow * AP + ks * 16 + lk * 8) * 2);
    }

    float o[16][4] = {};
    float m0v = -1e30f, m1v = -1e30f, l0v = 0.f, l1v = 0.f;

    for (int kb = kb0; kb < kbend; kb++) {
        const int i = kb - kb0;
        if (kb + 1 < kbend) {
            issueKV(kb + 1, (i + 1) & 1);
            cp_wait1();
        } else {
            cp_wait0();
        }
        __syncthreads();

        const uint32_t bK = sb + Q_BYTES + (i & 1) * KV_STAGE;
        const uint32_t bV = bK + Q_BYTES;

        // S = Q K^T
        float s[8][4] = {};
        #pragma unroll
        for (int ks = 0; ks < 8; ks++) {
            #pragma unroll
            for (int tp = 0; tp < 4; tp++) {
                uint32_t bf[4];
                ldsm4(bf, bK + (uint32_t)((tp * 16 + l8 + lk * 8) * AP
                                          + ks * 16 + lbit * 8) * 2);
                mma_f16(s[2 * tp],     qf[ks], bf);
                mma_f16(s[2 * tp + 1], qf[ks], bf + 2);
            }
        }

        if (kb == qb) {
            const int r0 = w * 16 + lq, r1 = r0 + 8;
            #pragma unroll
            for (int t = 0; t < 8; t++) {
                int c0 = t * 8 + lc * 2;
                if (c0 > r0)     s[t][0] = -1e30f;
                if (c0 + 1 > r0) s[t][1] = -1e30f;
                if (c0 > r1)     s[t][2] = -1e30f;
                if (c0 + 1 > r1) s[t][3] = -1e30f;
            }
        }

        // Online softmax
        float mx0 = -1e30f, mx1 = -1e30f;
        #pragma unroll
        for (int t = 0; t < 8; t++) {
            mx0 = fmaxf(mx0, fmaxf(s[t][0], s[t][1]));
            mx1 = fmaxf(mx1, fmaxf(s[t][2], s[t][3]));
        }
        mx0 = fmaxf(mx0, __shfl_xor_sync(~0u, mx0, 1));
        mx0 = fmaxf(mx0, __shfl_xor_sync(~0u, mx0, 2));
        mx1 = fmaxf(mx1, __shfl_xor_sync(~0u, mx1, 1));
        mx1 = fmaxf(mx1, __shfl_xor_sync(~0u, mx1, 2));
        float mn0 = fmaxf(m0v, mx0), mn1 = fmaxf(m1v, mx1);
        float sc0 = __expf(m0v - mn0), sc1 = __expf(m1v - mn1);
        float sum0 = 0.f, sum1 = 0.f;
        #pragma unroll
        for (int t = 0; t < 8; t++) {
            s[t][0] = __expf(s[t][0] - mn0);
            s[t][1] = __expf(s[t][1] - mn0);
            s[t][2] = __expf(s[t][2] - mn1);
            s[t][3] = __expf(s[t][3] - mn1);
            sum0 += s[t][0] + s[t][1];
            sum1 += s[t][2] + s[t][3];
        }
        sum0 += __shfl_xor_sync(~0u, sum0, 1);
        sum0 += __shfl_xor_sync(~0u, sum0, 2);
        sum1 += __shfl_xor_sync(~0u, sum1, 1);
        sum1 += __shfl_xor_sync(~0u, sum1, 2);
        l0v = l0v * sc0 + sum0;  l1v = l1v * sc1 + sum1;
        m0v = mn0;  m1v = mn1;
        #pragma unroll
        for (int t = 0; t < 16; t++) {
            o[t][0] *= sc0; o[t][1] *= sc0;
            o[t][2] *= sc1; o[t][3] *= sc1;
        }

        // P -> fp16 A fragments
        uint32_t pa[4][4];
        #pragma unroll
        for (int c = 0; c < 4; c++) {
            pa[c][0] = packh2(s[2 * c][0],     s[2 * c][1]);
            pa[c][1] = packh2(s[2 * c][2],     s[2 * c][3]);
            pa[c][2] = packh2(s[2 * c + 1][0], s[2 * c + 1][1]);
            pa[c][3] = packh2(s[2 * c + 1][2], s[2 * c + 1][3]);
        }

        // O += P @ V
        #pragma unroll
        for (int c = 0; c < 4; c++) {
            #pragma unroll
            for (int dp = 0; dp < 8; dp++) {
                uint32_t vf[4];
                ldsm4t(vf, bV + (uint32_t)((c * 16 + l8 + lbit * 8) * AP
                                           + dp * 16 + lk * 8) * 2);
                mma_f16(o[2 * dp],     pa[c], vf);
                mma_f16(o[2 * dp + 1], pa[c], vf + 2);
            }
        }
        __syncthreads();
    }

    const int lr0 = w * 16 + lq, lr1 = lr0 + 8;

    if (nsplit == 1) {
        const float inv0 = 1.f / l0v, inv1 = 1.f / l1v;
        const size_t gr0 = rowbase + q0 + lr0;
        #pragma unroll
        for (int t = 0; t < 16; t++) {
            int col = t * 8 + lc * 2;
            store_hilo2(o[t][0] * inv0, o[t][1] * inv0,
                        aoh + gr0 * DINNER + col, aol + gr0 * DINNER + col);
            store_hilo2(o[t][2] * inv1, o[t][3] * inv1,
                        aoh + (gr0 + 8) * DINNER + col,
                        aol + (gr0 + 8) * DINNER + col);
        }
    } else {
        const size_t pidx = ((size_t)(b * 64 + qb)) * 4 + sp;
        float* pob = po + pidx * (64 * DINNER);
        #pragma unroll
        for (int t = 0; t < 16; t++) {
            int col = t * 8 + lc * 2;
            float2 v0; v0.x = o[t][0]; v0.y = o[t][1];
            float2 v1; v1.x = o[t][2]; v1.y = o[t][3];
            *(float2*)(pob + lr0 * DINNER + col) = v0;
            *(float2*)(pob + lr1 * DINNER + col) = v1;
        }
        if (lc == 0) {
            pm[pidx * 64 + lr0] = m0v;  pm[pidx * 64 + lr1] = m1v;
            pl[pidx * 64 + lr0] = l0v;  pl[pidx * 64 + lr1] = l1v;
        }
    }
}

// Combine partials -> bf16 hi/lo attention output
__global__ __launch_bounds__(256) void attn_combine(
    const float* __restrict__ po, const float* __restrict__ pm,
    const float* __restrict__ pl,
    __nv_bfloat16* __restrict__ aoh, __nv_bfloat16* __restrict__ aol)
{
    const int qb = blockIdx.x, b = blockIdx.y;
    const int nsplit = (qb >> 4) + 1;
    if (nsplit < 2) return;
    const int t = threadIdx.x;
    const int r = t >> 2, c0 = (t & 3) * 32;
    const size_t base = ((size_t)(b * 64 + qb)) * 4;

    float mg = -1e30f;
    #pragma unroll
    for (int s = 0; s < 4; s++)
        if (s < nsplit) mg = fmaxf(mg, pm[(base + s) * 64 + r]);
    float wgt[4] = {};
    float L = 0.f;
    #pragma unroll
    for (int s = 0; s < 4; s++)
        if (s < nsplit) {
            wgt[s] = __expf(pm[(base + s) * 64 + r] - mg);
            L += wgt[s] * pl[(base + s) * 64 + r];
        }
    const float inv = 1.f / L;
    const size_t grow = (size_t)b * SEQ + qb * 64 + r;

    for (int c = c0; c < c0 + 32; c += 2) {
        float ax = 0.f, ay = 0.f;
        #pragma unroll
        for (int s = 0; s < 4; s++)
            if (s < nsplit) {
                const float2 v = *(const float2*)(po + (base + s) * (64 * DINNER)
                                                  + r * DINNER + c);
                ax += wgt[s] * v.x;  ay += wgt[s] * v.y;
            }
        store_hilo2(ax * inv, ay * inv,
                    aoh + grow * DINNER + c, aol + grow * DINNER + c);
    }
}

// ---------------------------------------------------------------------------
extern "C" void kernel_launch(void* const* d_in, const int* in_sizes, int n_in,
                              void* d_out, int out_size)
{
    const float* x     = (const float*)d_in[0];
    const float* w_qkv = (const float*)d_in[1];
    const float* w_out = (const float*)d_in[2];
    const float* b_out = (const float*)d_in[3];
    float* out = (float*)d_out;

    __nv_bfloat16 *xh, *xl, *wqh, *wql, *woh, *wol, *aoh, *aol;
    __half *q_p, *k_p, *v_p;
    float *po, *pmv, *plv;
    cudaGetSymbolAddress((void**)&xh, g_xh);
    cudaGetSymbolAddress((void**)&xl, g_xl);
    cudaGetSymbolAddress((void**)&wqh, g_wqh);
    cudaGetSymbolAddress((void**)&wql, g_wql);
    cudaGetSymbolAddress((void**)&woh, g_woh);
    cudaGetSymbolAddress((void**)&wol, g_wol);
    cudaGetSymbolAddress((void**)&aoh, g_aoh);
    cudaGetSymbolAddress((void**)&aol, g_aol);
    cudaGetSymbolAddress((void**)&q_p, g_q);
    cudaGetSymbolAddress((void**)&k_p, g_k);
    cudaGetSymbolAddress((void**)&v_p, g_v);
    cudaGetSymbolAddress((void**)&po, g_po);
    cudaGetSymbolAddress((void**)&pmv, g_pm);
    cudaGetSymbolAddress((void**)&plv, g_pl);

    cudaFuncSetAttribute(gemm_qkv, cudaFuncAttributeMaxDynamicSharedMemorySize,
                         GEMM_SMEM);
    cudaFuncSetAttribute(gemm_out, cudaFuncAttributeMaxDynamicSharedMemorySize,
                         GEMM_SMEM);
    cudaFuncSetAttribute(attn_part, cudaFuncAttributeMaxDynamicSharedMemorySize,
                         ATTN_SMEM);

    // 0) Pre-split fp32 -> bf16 hi/lo
    split_fp32<<<(M_TOTAL * DIN / 4 + 255) / 256, 256>>>(x, xh, xl,
                                                         M_TOTAL * DIN / 4);
    split_fp32<<<(QKVN * DIN / 4 + 255) / 256, 256>>>(w_qkv, wqh, wql,
                                                      QKVN * DIN / 4);
    split_fp32<<<(DOUT * DINNER / 4 + 255) / 256, 256>>>(w_out, woh, wol,
                                                         DOUT * DINNER / 4);

    // 1) QKV projection -> fp16 q(scaled)/k/v
    gemm_qkv<<<dim3(QKVN / 128, M_TOTAL / 128), 256, GEMM_SMEM>>>(
        xh, xl, wqh, wql);

    // 2) Split-K causal flash attention
    attn_part<<<dim3(SEQ / 64, 4, BATCH), 128, ATTN_SMEM>>>(
        q_p, k_p, v_p, aoh, aol, po, pmv, plv);
    attn_combine<<<dim3(SEQ / 64, BATCH), 256>>>(po, pmv, plv, aoh, aol);

    // 3) Output projection + bias
    gemm_out<<<dim3(DOUT / 128, M_TOTAL / 128), 256, GEMM_SMEM>>>(
        aoh, aol, woh, wol, b_out, out);
}

// round 6
// speedup vs baseline: 10.3861x; 1.1783x over previous
#include <cuda_runtime.h>
#include <cuda_fp16.h>
#include <cstdint>

#define BATCH   4
#define SEQ     4096
#define DIN     1024
#define DINNER  128
#define DOUT    1024
#define QKVN    384
#define M_TOTAL (BATCH * SEQ)
// SCALE * log2(e): softmax runs in base-2 domain
#define QSCL    0.12751744f

// Scratch
__device__ __half g_x16[(size_t)M_TOTAL * DIN];
__device__ __half g_wqh[QKVN * DIN];
__device__ __half g_wql[QKVN * DIN];
__device__ __half g_woh[DOUT * DINNER];
__device__ __half g_wol[DOUT * DINNER];
__device__ __half g_q[(size_t)M_TOTAL * DINNER];
__device__ __half g_k[(size_t)M_TOTAL * DINNER];
__device__ __half g_v[(size_t)M_TOTAL * DINNER];
__device__ __half g_ao[(size_t)M_TOTAL * DINNER];
__device__ float g_po[(size_t)BATCH * 64 * 4 * 64 * DINNER];
__device__ float g_pm[BATCH * 64 * 4 * 64];
__device__ float g_pl[BATCH * 64 * 4 * 64];

// ---------------------------------------------------------------------------
// PTX helpers
// ---------------------------------------------------------------------------
__device__ __forceinline__ uint32_t smem_u32(const void* p) {
    uint32_t a;
    asm("{ .reg .u64 t; cvta.to.shared.u64 t, %1; cvt.u32.u64 %0, t; }"
        : "=r"(a) : "l"(p));
    return a;
}
__device__ __forceinline__ void cpa16(uint32_t dst, const void* src) {
    asm volatile("cp.async.cg.shared.global [%0], [%1], 16;"
                 :: "r"(dst), "l"(src));
}
__device__ __forceinline__ void cp_commit() {
    asm volatile("cp.async.commit_group;" ::: "memory");
}
__device__ __forceinline__ void cp_wait1() {
    asm volatile("cp.async.wait_group 1;" ::: "memory");
}
__device__ __forceinline__ void cp_wait0() {
    asm volatile("cp.async.wait_group 0;" ::: "memory");
}
__device__ __forceinline__ void ldsm4(uint32_t* r, uint32_t a) {
    asm volatile("ldmatrix.sync.aligned.m8n8.x4.shared.b16 {%0,%1,%2,%3}, [%4];"
        : "=r"(r[0]), "=r"(r[1]), "=r"(r[2]), "=r"(r[3]) : "r"(a));
}
__device__ __forceinline__ void ldsm4t(uint32_t* r, uint32_t a) {
    asm volatile("ldmatrix.sync.aligned.m8n8.x4.trans.shared.b16 {%0,%1,%2,%3}, [%4];"
        : "=r"(r[0]), "=r"(r[1]), "=r"(r[2]), "=r"(r[3]) : "r"(a));
}
__device__ __forceinline__ void ldsm2(uint32_t* r, uint32_t a) {
    asm volatile("ldmatrix.sync.aligned.m8n8.x2.shared.b16 {%0,%1}, [%2];"
        : "=r"(r[0]), "=r"(r[1]) : "r"(a));
}
__device__ __forceinline__ void mma_f16(float* c, const uint32_t* a,
                                        const uint32_t* b) {
    asm volatile(
        "mma.sync.aligned.m16n8k16.row.col.f32.f16.f16.f32 "
        "{%0,%1,%2,%3}, {%4,%5,%6,%7}, {%8,%9}, {%0,%1,%2,%3};"
        : "+f"(c[0]), "+f"(c[1]), "+f"(c[2]), "+f"(c[3])
        : "r"(a[0]), "r"(a[1]), "r"(a[2]), "r"(a[3]), "r"(b[0]), "r"(b[1]));
}
__device__ __forceinline__ uint32_t packh2(float a, float b) {
    __half2 h = __floats2half2_rn(a, b);
    return *(uint32_t*)&h;
}
__device__ __forceinline__ float ex2(float x) {
    float y;
    asm("ex2.approx.f32 %0, %1;" : "=f"(y) : "f"(x));
    return y;
}

// ---------------------------------------------------------------------------
// Conversions
// ---------------------------------------------------------------------------
__global__ __launch_bounds__(256) void to_fp16(
    const float* __restrict__ src, __half* __restrict__ dst, int n4)
{
    int i = blockIdx.x * 256 + threadIdx.x;
    if (i >= n4) return;
    float4 f = ((const float4*)src)[i];
    __half2 a = __floats2half2_rn(f.x, f.y);
    __half2 b = __floats2half2_rn(f.z, f.w);
    uint2 v; v.x = *(uint32_t*)&a; v.y = *(uint32_t*)&b;
    *(uint2*)(dst + i * 4) = v;
}

__global__ __launch_bounds__(256) void split_w16(
    const float* __restrict__ src, __half* __restrict__ hi,
    __half* __restrict__ lo, int n4)
{
    int i = blockIdx.x * 256 + threadIdx.x;
    if (i >= n4) return;
    float4 f = ((const float4*)src)[i];
    __half2 h0 = __floats2half2_rn(f.x, f.y);
    __half2 h1 = __floats2half2_rn(f.z, f.w);
    __half2 l0 = __floats2half2_rn(f.x - __half2float(h0.x),
                                   f.y - __half2float(h0.y));
    __half2 l1 = __floats2half2_rn(f.z - __half2float(h1.x),
                                   f.w - __half2float(h1.y));
    uint2 hv; hv.x = *(uint32_t*)&h0; hv.y = *(uint32_t*)&h1;
    uint2 lv; lv.x = *(uint32_t*)&l0; lv.y = *(uint32_t*)&l1;
    *(uint2*)(hi + i * 4) = hv;
    *(uint2*)(lo + i * 4) = lv;
}

// ---------------------------------------------------------------------------
// fp16x2 GEMM with cp.async double-buffering. Tile 128x128x32, 256 threads.
//   C[m,n] = A[m,:]·(Bh[n,:]+Bl[n,:]),  A fp16, Bh/Bl fp16 (weight hi/lo).
// ---------------------------------------------------------------------------
#define PITCH 40
#define ARR_H 10240          // one 128x40 fp16 array (bytes)
#define STG_H (3 * ARR_H)    // stage: A, Bh, Bl
#define GEMM_SMEM (2 * STG_H)

struct GemmFrag { float acc[4][4][4]; };

__device__ __forceinline__ void gemm2_issue(
    const __half* A, const __half* Bh, const __half* Bl,
    int K, int m0, int n0, int k0, uint32_t stage, int tid)
{
    const int row = tid >> 1, cc = (tid & 1) * 16;
    const uint32_t d0 = (uint32_t)(row * PITCH + cc) * 2;
    const uint32_t d1 = (uint32_t)(row * PITCH + cc + 8) * 2;
    const __half* a  = A  + (size_t)(m0 + row) * K + k0 + cc;
    const __half* bh = Bh + (size_t)(n0 + row) * K + k0 + cc;
    const __half* bl = Bl + (size_t)(n0 + row) * K + k0 + cc;
    cpa16(stage + d0, a);                 cpa16(stage + d1, a + 8);
    cpa16(stage + ARR_H + d0, bh);        cpa16(stage + ARR_H + d1, bh + 8);
    cpa16(stage + 2 * ARR_H + d0, bl);    cpa16(stage + 2 * ARR_H + d1, bl + 8);
    cp_commit();
}

__device__ __forceinline__ void gemm2_mainloop(
    GemmFrag& fr, const __half* A, const __half* Bh, const __half* Bl,
    int K, int m0, int n0, uint32_t sb, int tid)
{
    const int lid = tid & 31, wid = tid >> 5;
    const int mbase = (wid & 1) * 64, nbase = (wid >> 1) * 32;
    const int l8 = lid & 7, lbit = (lid >> 3) & 1, lk = lid >> 4;
    const int nk = K >> 5;

    gemm2_issue(A, Bh, Bl, K, m0, n0, 0, sb, tid);

    for (int it = 0; it < nk; it++) {
        if (it + 1 < nk) {
            gemm2_issue(A, Bh, Bl, K, m0, n0, (it + 1) << 5,
                        sb + ((it + 1) & 1) * STG_H, tid);
            cp_wait1();
        } else {
            cp_wait0();
        }
        __syncthreads();

        const uint32_t base = sb + (it & 1) * STG_H;
        const uint32_t aA = base, aBh = base + ARR_H, aBl = base + 2 * ARR_H;

        #pragma unroll
        for (int ks = 0; ks < 32; ks += 16) {
            uint32_t af[4][4], bh[4][2], bl[4][2];
            #pragma unroll
            for (int tm = 0; tm < 4; tm++) {
                uint32_t off = (uint32_t)((mbase + tm * 16 + l8 + lbit * 8) * PITCH
                                          + ks + lk * 8) * 2;
                ldsm4(af[tm], aA + off);
            }
            #pragma unroll
            for (int tn = 0; tn < 4; tn++) {
                uint32_t off = (uint32_t)((nbase + tn * 8 + l8) * PITCH
                                          + ks + lbit * 8) * 2;
                ldsm2(bh[tn], aBh + off);
                ldsm2(bl[tn], aBl + off);
            }
            #pragma unroll
            for (int tm = 0; tm < 4; tm++)
                #pragma unroll
                for (int tn = 0; tn < 4; tn++) {
                    mma_f16(fr.acc[tm][tn], af[tm], bh[tn]);
                    mma_f16(fr.acc[tm][tn], af[tm], bl[tn]);
                }
        }
        __syncthreads();
    }
}

// QKV GEMM: epilogue writes fp16 q(scaled by QSCL)/k/v
__global__ __launch_bounds__(256, 2) void gemm_qkv(
    const __half* __restrict__ A, const __half* __restrict__ Bh,
    const __half* __restrict__ Bl)
{
    extern __shared__ char smc[];
    const uint32_t sb = smem_u32(smc);
    const int tid = threadIdx.x, lid = tid & 31, wid = tid >> 5;
    const int m0 = blockIdx.y * 128, n0 = blockIdx.x * 128;
    const int mbase = (wid & 1) * 64, nbase = (wid >> 1) * 32;

    GemmFrag fr = {};
    gemm2_mainloop(fr, A, Bh, Bl, DIN, m0, n0, sb, tid);

    __half* dst = (blockIdx.x == 0) ? g_q : (blockIdx.x == 1 ? g_k : g_v);
    const float scl = (blockIdx.x == 0) ? QSCL : 1.0f;
    #pragma unroll
    for (int tn = 0; tn < 4; tn++) {
        int gc = nbase + tn * 8 + (lid & 3) * 2;
        #pragma unroll
        for (int tm = 0; tm < 4; tm++) {
            int gr = m0 + mbase + tm * 16 + (lid >> 2);
            __half2 h0 = __floats2half2_rn(fr.acc[tm][tn][0] * scl,
                                           fr.acc[tm][tn][1] * scl);
            __half2 h1 = __floats2half2_rn(fr.acc[tm][tn][2] * scl,
                                           fr.acc[tm][tn][3] * scl);
            *(__half2*)(dst + (size_t)gr * DINNER + gc) = h0;
            *(__half2*)(dst + (size_t)(gr + 8) * DINNER + gc) = h1;
        }
    }
}

// Out GEMM: fp32 + bias
__global__ __launch_bounds__(256, 2) void gemm_out(
    const __half* __restrict__ A, const __half* __restrict__ Bh,
    const __half* __restrict__ Bl,
    const float* __restrict__ bias, float* __restrict__ C)
{
    extern __shared__ char smc[];
    const uint32_t sb = smem_u32(smc);
    const int tid = threadIdx.x, lid = tid & 31, wid = tid >> 5;
    const int m0 = blockIdx.y * 128, n0 = blockIdx.x * 128;
    const int mbase = (wid & 1) * 64, nbase = (wid >> 1) * 32;

    GemmFrag fr = {};
    gemm2_mainloop(fr, A, Bh, Bl, DINNER, m0, n0, sb, tid);

    #pragma unroll
    for (int tn = 0; tn < 4; tn++) {
        int gc = n0 + nbase + tn * 8 + (lid & 3) * 2;
        float bx = bias[gc], by = bias[gc + 1];
        #pragma unroll
        for (int tm = 0; tm < 4; tm++) {
            int gr = m0 + mbase + tm * 16 + (lid >> 2);
            float2 v0, v1;
            v0.x = fr.acc[tm][tn][0] + bx; v0.y = fr.acc[tm][tn][1] + by;
            v1.x = fr.acc[tm][tn][2] + bx; v1.y = fr.acc[tm][tn][3] + by;
            *(float2*)(C + (size_t)gr * DOUT + gc) = v0;
            *(float2*)(C + (size_t)(gr + 8) * DOUT + gc) = v1;
        }
    }
}

// ---------------------------------------------------------------------------
// Split-K flash attention (causal), mma.sync fp16, base-2 softmax.
// Grid (64 qtiles, 4 splits, 4 batch); split = 16 key-tiles (1024 keys).
// ---------------------------------------------------------------------------
#define AP 136
#define Q_BYTES  (64 * AP * 2)
#define KV_STAGE (2 * Q_BYTES)
#define ATTN_SMEM (Q_BYTES + 2 * KV_STAGE)

__global__ __launch_bounds__(128, 2) void attn_part(
    const __half* __restrict__ gq, const __half* __restrict__ gk,
    const __half* __restrict__ gv, __half* __restrict__ ao,
    float* __restrict__ po, float* __restrict__ pm, float* __restrict__ pl)
{
    extern __shared__ char smc[];
    const int qb = blockIdx.x, sp = blockIdx.y, b = blockIdx.z;
    const int ntiles = qb + 1;
    const int kb0 = sp * 16;
    if (kb0 >= ntiles) return;
    const int kbend = (kb0 + 16 < ntiles) ? (kb0 + 16) : ntiles;
    const int nsplit = (qb >> 4) + 1;

    const int tid = threadIdx.x, lid = tid & 31, w = tid >> 5;
    const int q0 = qb * 64;
    const int l8 = lid & 7, lbit = (lid >> 3) & 1, lk = lid >> 4;
    const int lq = lid >> 2, lc = lid & 3;
    const size_t rowbase = (size_t)b * SEQ;
    const uint32_t sb = smem_u32(smc);
    __half* sQ = (__half*)smc;

    const int r0c = tid >> 4, cc = tid & 15;

    auto issueKV = [&](int kb, int st) {
        const __half* srcK = gk + (rowbase + (size_t)kb * 64) * DINNER;
        const __half* srcV = gv + (rowbase + (size_t)kb * 64) * DINNER;
        uint32_t dK = sb + Q_BYTES + st * KV_STAGE;
        uint32_t dV = dK + Q_BYTES;
        #pragma unroll
        for (int j = 0; j < 8; j++) {
            int row = r0c + j * 8;
            uint32_t doff = (uint32_t)(row * AP + cc * 8) * 2;
            cpa16(dK + doff, srcK + row * DINNER + cc * 8);
            cpa16(dV + doff, srcV + row * DINNER + cc * 8);
        }
        cp_commit();
    };

    issueKV(kb0, 0);

    #pragma unroll
    for (int i = 0; i < 8; i++) {
        int idx = i * 128 + tid;
        int r = idx >> 4, c = idx & 15;
        *(uint4*)(sQ + r * AP + c * 8) =
            *(const uint4*)(gq + (rowbase + q0 + r) * DINNER + c * 8);
    }
    __syncthreads();

    uint32_t qf[8][4];
    {
        const int arow = w * 16 + l8 + lbit * 8;
        #pragma unroll
        for (int ks = 0; ks < 8; ks++)
            ldsm4(qf[ks], sb + (uint32_t)(arow * AP + ks * 16 + lk * 8) * 2);
    }

    float o[16][4] = {};
    float m0v = -1e30f, m1v = -1e30f, l0v = 0.f, l1v = 0.f;

    for (int kb = kb0; kb < kbend; kb++) {
        const int i = kb - kb0;
        if (kb + 1 < kbend) {
            issueKV(kb + 1, (i + 1) & 1);
            cp_wait1();
        } else {
            cp_wait0();
        }
        __syncthreads();

        const uint32_t bK = sb + Q_BYTES + (i & 1) * KV_STAGE;
        const uint32_t bV = bK + Q_BYTES;

        float s[8][4] = {};
        #pragma unroll
        for (int ks = 0; ks < 8; ks++) {
            #pragma unroll
            for (int tp = 0; tp < 4; tp++) {
                uint32_t bf[4];
                ldsm4(bf, bK + (uint32_t)((tp * 16 + l8 + lk * 8) * AP
                                          + ks * 16 + lbit * 8) * 2);
                mma_f16(s[2 * tp],     qf[ks], bf);
                mma_f16(s[2 * tp + 1], qf[ks], bf + 2);
            }
        }

        if (kb == qb) {
            const int r0 = w * 16 + lq, r1 = r0 + 8;
            #pragma unroll
            for (int t = 0; t < 8; t++) {
                int c0 = t * 8 + lc * 2;
                if (c0 > r0)     s[t][0] = -1e30f;
                if (c0 + 1 > r0) s[t][1] = -1e30f;
                if (c0 > r1)     s[t][2] = -1e30f;
                if (c0 + 1 > r1) s[t][3] = -1e30f;
            }
        }

        float mx0 = -1e30f, mx1 = -1e30f;
        #pragma unroll
        for (int t = 0; t < 8; t++) {
            mx0 = fmaxf(mx0, fmaxf(s[t][0], s[t][1]));
            mx1 = fmaxf(mx1, fmaxf(s[t][2], s[t][3]));
        }
        mx0 = fmaxf(mx0, __shfl_xor_sync(~0u, mx0, 1));
        mx0 = fmaxf(mx0, __shfl_xor_sync(~0u, mx0, 2));
        mx1 = fmaxf(mx1, __shfl_xor_sync(~0u, mx1, 1));
        mx1 = fmaxf(mx1, __shfl_xor_sync(~0u, mx1, 2));
        float mn0 = fmaxf(m0v, mx0), mn1 = fmaxf(m1v, mx1);
        float sc0 = ex2(m0v - mn0), sc1 = ex2(m1v - mn1);
        float sum0 = 0.f, sum1 = 0.f;
        #pragma unroll
        for (int t = 0; t < 8; t++) {
            s[t][0] = ex2(s[t][0] - mn0);
            s[t][1] = ex2(s[t][1] - mn0);
            s[t][2] = ex2(s[t][2] - mn1);
            s[t][3] = ex2(s[t][3] - mn1);
            sum0 += s[t][0] + s[t][1];
            sum1 += s[t][2] + s[t][3];
        }
        sum0 += __shfl_xor_sync(~0u, sum0, 1);
        sum0 += __shfl_xor_sync(~0u, sum0, 2);
        sum1 += __shfl_xor_sync(~0u, sum1, 1);
        sum1 += __shfl_xor_sync(~0u, sum1, 2);
        l0v = l0v * sc0 + sum0;  l1v = l1v * sc1 + sum1;
        m0v = mn0;  m1v = mn1;
        #pragma unroll
        for (int t = 0; t < 16; t++) {
            o[t][0] *= sc0; o[t][1] *= sc0;
            o[t][2] *= sc1; o[t][3] *= sc1;
        }

        uint32_t pa[4][4];
        #pragma unroll
        for (int c = 0; c < 4; c++) {
            pa[c][0] = packh2(s[2 * c][0],     s[2 * c][1]);
            pa[c][1] = packh2(s[2 * c][2],     s[2 * c][3]);
            pa[c][2] = packh2(s[2 * c + 1][0], s[2 * c + 1][1]);
            pa[c][3] = packh2(s[2 * c + 1][2], s[2 * c + 1][3]);
        }

        #pragma unroll
        for (int c = 0; c < 4; c++) {
            #pragma unroll
            for (int dp = 0; dp < 8; dp++) {
                uint32_t vf[4];
                ldsm4t(vf, bV + (uint32_t)((c * 16 + l8 + lbit * 8) * AP
                                           + dp * 16 + lk * 8) * 2);
                mma_f16(o[2 * dp],     pa[c], vf);
                mma_f16(o[2 * dp + 1], pa[c], vf + 2);
            }
        }
        __syncthreads();
    }

    const int lr0 = w * 16 + lq, lr1 = lr0 + 8;

    if (nsplit == 1) {
        const float inv0 = 1.f / l0v, inv1 = 1.f / l1v;
        const size_t gr0 = rowbase + q0 + lr0;
        #pragma unroll
        for (int t = 0; t < 16; t++) {
            int col = t * 8 + lc * 2;
            *(__half2*)(ao + gr0 * DINNER + col) =
                __floats2half2_rn(o[t][0] * inv0, o[t][1] * inv0);
            *(__half2*)(ao + (gr0 + 8) * DINNER + col) =
                __floats2half2_rn(o[t][2] * inv1, o[t][3] * inv1);
        }
    } else {
        const size_t pidx = ((size_t)(b * 64 + qb)) * 4 + sp;
        float* pob = po + pidx * (64 * DINNER);
        #pragma unroll
        for (int t = 0; t < 16; t++) {
            int col = t * 8 + lc * 2;
            float2 v0; v0.x = o[t][0]; v0.y = o[t][1];
            float2 v1; v1.x = o[t][2]; v1.y = o[t][3];
            *(float2*)(pob + lr0 * DINNER + col) = v0;
            *(float2*)(pob + lr1 * DINNER + col) = v1;
        }
        if (lc == 0) {
            pm[pidx * 64 + lr0] = m0v;  pm[pidx * 64 + lr1] = m1v;
            pl[pidx * 64 + lr0] = l0v;  pl[pidx * 64 + lr1] = l1v;
        }
    }
}

// Combine partials -> fp16 attention output
__global__ __launch_bounds__(256) void attn_combine(
    const float* __restrict__ po, const float* __restrict__ pm,
    const float* __restrict__ pl, __half* __restrict__ ao)
{
    const int qb = blockIdx.x, b = blockIdx.y;
    const int nsplit = (qb >> 4) + 1;
    if (nsplit < 2) return;
    const int t = threadIdx.x;
    const int r = t >> 2, c0 = (t & 3) * 32;
    const size_t base = ((size_t)(b * 64 + qb)) * 4;

    float mg = -1e30f;
    #pragma unroll
    for (int s = 0; s < 4; s++)
        if (s < nsplit) mg = fmaxf(mg, pm[(base + s) * 64 + r]);
    float wgt[4] = {};
    float L = 0.f;
    #pragma unroll
    for (int s = 0; s < 4; s++)
        if (s < nsplit) {
            wgt[s] = ex2(pm[(base + s) * 64 + r] - mg);
            L += wgt[s] * pl[(base + s) * 64 + r];
        }
    const float inv = 1.f / L;
    const size_t grow = (size_t)b * SEQ + qb * 64 + r;

    for (int c = c0; c < c0 + 32; c += 2) {
        float ax = 0.f, ay = 0.f;
        #pragma unroll
        for (int s = 0; s < 4; s++)
            if (s < nsplit) {
                const float2 v = *(const float2*)(po + (base + s) * (64 * DINNER)
                                                  + r * DINNER + c);
                ax += wgt[s] * v.x;  ay += wgt[s] * v.y;
            }
        *(__half2*)(ao + grow * DINNER + c) =
            __floats2half2_rn(ax * inv, ay * inv);
    }
}

// ---------------------------------------------------------------------------
extern "C" void kernel_launch(void* const* d_in, const int* in_sizes, int n_in,
                              void* d_out, int out_size)
{
    const float* x     = (const float*)d_in[0];
    const float* w_qkv = (const float*)d_in[1];
    const float* w_out = (const float*)d_in[2];
    const float* b_out = (const float*)d_in[3];
    float* out = (float*)d_out;

    __half *x16, *wqh, *wql, *woh, *wol, *q_p, *k_p, *v_p, *ao;
    float *po, *pmv, *plv;
    cudaGetSymbolAddress((void**)&x16, g_x16);
    cudaGetSymbolAddress((void**)&wqh, g_wqh);
    cudaGetSymbolAddress((void**)&wql, g_wql);
    cudaGetSymbolAddress((void**)&woh, g_woh);
    cudaGetSymbolAddress((void**)&wol, g_wol);
    cudaGetSymbolAddress((void**)&q_p, g_q);
    cudaGetSymbolAddress((void**)&k_p, g_k);
    cudaGetSymbolAddress((void**)&v_p, g_v);
    cudaGetSymbolAddress((void**)&ao, g_ao);
    cudaGetSymbolAddress((void**)&po, g_po);
    cudaGetSymbolAddress((void**)&pmv, g_pm);
    cudaGetSymbolAddress((void**)&plv, g_pl);

    cudaFuncSetAttribute(gemm_qkv, cudaFuncAttributeMaxDynamicSharedMemorySize,
                         GEMM_SMEM);
    cudaFuncSetAttribute(gemm_out, cudaFuncAttributeMaxDynamicSharedMemorySize,
                         GEMM_SMEM);
    cudaFuncSetAttribute(attn_part, cudaFuncAttributeMaxDynamicSharedMemorySize,
                         ATTN_SMEM);

    // 0) Conversions: x -> fp16; weights -> fp16 hi/lo
    to_fp16<<<(M_TOTAL * DIN / 4 + 255) / 256, 256>>>(x, x16, M_TOTAL * DIN / 4);
    split_w16<<<(QKVN * DIN / 4 + 255) / 256, 256>>>(w_qkv, wqh, wql,
                                                     QKVN * DIN / 4);
    split_w16<<<(DOUT * DINNER / 4 + 255) / 256, 256>>>(w_out, woh, wol,
                                                        DOUT * DINNER / 4);

    // 1) QKV projection -> fp16 q(scaled)/k/v
    gemm_qkv<<<dim3(QKVN / 128, M_TOTAL / 128), 256, GEMM_SMEM>>>(
        x16, wqh, wql);

    // 2) Split-K causal flash attention -> fp16
    attn_part<<<dim3(SEQ / 64, 4, BATCH), 128, ATTN_SMEM>>>(
        q_p, k_p, v_p, ao, po, pmv, plv);
    attn_combine<<<dim3(SEQ / 64, BATCH), 256>>>(po, pmv, plv, ao);

    // 3) Output projection + bias
    gemm_out<<<dim3(DOUT / 128, M_TOTAL / 128), 256, GEMM_SMEM>>>(
        ao, woh, wol, b_out, out);
}